// round 3
// baseline (speedup 1.0000x reference)
#include <cuda_runtime.h>
#include <math.h>

#define TS 1024
#define TB 8
#define TE 512
#define TDH 256
#define TSW 96
#define NTOK 8192

__device__ __align__(16) float g_qkv [(size_t)NTOK*1536];
__device__ __align__(16) float g_ao  [(size_t)NTOK*TE];
__device__ __align__(16) float g_proj[(size_t)NTOK*TE];
__device__ __align__(16) float g_x1  [(size_t)NTOK*TE];
__device__ __align__(16) float g_lg  [(size_t)NTOK*128];
__device__ __align__(16) float g_x2  [(size_t)NTOK*TE];
__device__ __align__(16) float g_ffh [(size_t)NTOK*2048];
__device__ __align__(16) float g_ffo [(size_t)NTOK*TE];

__device__ __forceinline__ float nonsat_f(float x) {
    float y = x;
#pragma unroll 1
    for (int it = 0; it < 32; ++it) {
        float y2 = y * y;
        float yn = __fdividef(0.66666668f * y * y2 + x, y2 + 1.0f);
        float d = fabsf(yn - y);
        y = yn;
        if (d <= 1e-6f) break;
    }
    return y;
}

// C(MxN) = A(MxK) @ W(NxK)^T ; EPI 0:+bias 1:nonsat(+bias) 2:0.5*(acc+res)
template<int EPI>
__global__ void __launch_bounds__(256) gemm64(
    const float* __restrict__ A, const float* __restrict__ W,
    const float* __restrict__ bias, const float* __restrict__ res,
    float* __restrict__ C, int M, int N, int K)
{
    __shared__ __align__(16) float As[16][68];
    __shared__ __align__(16) float Bs[16][68];
    const int m0 = blockIdx.y * 64, n0 = blockIdx.x * 64;
    const int tid = threadIdx.x;
    const int lr = tid >> 2, lc = (tid & 3) << 2;
    const int tx = tid & 15, ty = tid >> 4;
    float acc[4][4];
#pragma unroll
    for (int i = 0; i < 4; i++)
#pragma unroll
        for (int j = 0; j < 4; j++) acc[i][j] = 0.f;
    const float* Ap = A + (size_t)(m0 + lr) * K + lc;
    const float* Wp = W + (size_t)(n0 + lr) * K + lc;
    for (int k0 = 0; k0 < K; k0 += 16) {
        float4 av = *(const float4*)(Ap + k0);
        float4 wv = *(const float4*)(Wp + k0);
        As[lc+0][lr]=av.x; As[lc+1][lr]=av.y; As[lc+2][lr]=av.z; As[lc+3][lr]=av.w;
        Bs[lc+0][lr]=wv.x; Bs[lc+1][lr]=wv.y; Bs[lc+2][lr]=wv.z; Bs[lc+3][lr]=wv.w;
        __syncthreads();
#pragma unroll
        for (int kk = 0; kk < 16; kk++) {
            float4 a = *(const float4*)&As[kk][ty<<2];
            float4 b = *(const float4*)&Bs[kk][tx<<2];
            float aa[4]={a.x,a.y,a.z,a.w}, bb[4]={b.x,b.y,b.z,b.w};
#pragma unroll
            for (int i = 0; i < 4; i++)
#pragma unroll
                for (int j = 0; j < 4; j++) acc[i][j] += aa[i]*bb[j];
        }
        __syncthreads();
    }
#pragma unroll
    for (int i = 0; i < 4; i++) {
        int m = m0 + (ty<<2) + i;
        float4 o; float* op = &o.x;
#pragma unroll
        for (int j = 0; j < 4; j++) {
            int n = n0 + (tx<<2) + j;
            float v = acc[i][j];
            if (EPI == 0)      v += bias[n];
            else if (EPI == 1) v = nonsat_f(v + bias[n]);
            else               v = 0.5f * (v + res[(size_t)m*N + n]);
            op[j] = v;
        }
        *(float4*)(C + (size_t)m*N + n0 + (tx<<2)) = o;
    }
}

__global__ void __launch_bounds__(256) attn_kernel(const float* __restrict__ qkv,
                                                   float* __restrict__ ao)
{
    __shared__ __align__(16) float Qs[64*68];
    __shared__ __align__(16) float Ks[32*68];
    __shared__ __align__(16) float Vs[32*68];
    __shared__ __align__(16) float Ps[64*36];
    const int q0 = blockIdx.x * 64;
    const int b  = blockIdx.y >> 3, h = blockIdx.y & 7;
    const int tid = threadIdx.x;
    const int r = tid >> 2, i = tid & 3;
    const int qg = q0 + r;
    {
        const float* src = qkv + ((size_t)qg*TB + b)*1536 + h*64 + (i<<4);
#pragma unroll
        for (int j = 0; j < 16; j += 4) {
            float4 v = *(const float4*)(src + j);
            Qs[r*68+(i<<4)+j]=v.x; Qs[r*68+(i<<4)+j+1]=v.y;
            Qs[r*68+(i<<4)+j+2]=v.z; Qs[r*68+(i<<4)+j+3]=v.w;
        }
    }
    float o[16];
#pragma unroll
    for (int d = 0; d < 16; d++) o[d] = 0.f;
    float m = -1e30f, l = 0.f;
    const int ntiles = (q0 >> 5) + 2;
    for (int kt = 0; kt < ntiles; kt++) {
        const int k0 = kt << 5;
        __syncthreads();
#pragma unroll
        for (int u2 = 0; u2 < 2; u2++) {
            int e4 = tid + (u2<<8);
            int kr = e4 >> 4, kc = (e4 & 15) << 2;
            const float* rowp = qkv + ((size_t)(k0+kr)*TB + b)*1536 + h*64;
            float4 kv = *(const float4*)(rowp + 512 + kc);
            float4 vv = *(const float4*)(rowp + 1024 + kc);
            Ks[kr*68+kc]=kv.x; Ks[kr*68+kc+1]=kv.y; Ks[kr*68+kc+2]=kv.z; Ks[kr*68+kc+3]=kv.w;
            Vs[kr*68+kc]=vv.x; Vs[kr*68+kc+1]=vv.y; Vs[kr*68+kc+2]=vv.z; Vs[kr*68+kc+3]=vv.w;
        }
        __syncthreads();
        float sc[8];
#pragma unroll
        for (int cc = 0; cc < 8; cc++) sc[cc] = 0.f;
#pragma unroll
        for (int kk = 0; kk < 64; kk += 4) {
            float4 q4 = *(const float4*)&Qs[r*68+kk];
#pragma unroll
            for (int cc = 0; cc < 8; cc++) {
                float4 k4 = *(const float4*)&Ks[(i*8+cc)*68+kk];
                sc[cc] += q4.x*k4.x + q4.y*k4.y + q4.z*k4.z + q4.w*k4.w;
            }
        }
        float tmax = -1e30f;
#pragma unroll
        for (int cc = 0; cc < 8; cc++) {
            sc[cc] = (k0 + i*8 + cc <= qg) ? sc[cc]*0.125f : -1e30f;
            tmax = fmaxf(tmax, sc[cc]);
        }
        tmax = fmaxf(tmax, __shfl_xor_sync(0xffffffffu, tmax, 1));
        tmax = fmaxf(tmax, __shfl_xor_sync(0xffffffffu, tmax, 2));
        float mnew = fmaxf(m, tmax);
        float scale = __expf(m - mnew);
        float psum = 0.f;
#pragma unroll
        for (int cc = 0; cc < 8; cc++) {
            float p = __expf(sc[cc] - mnew);
            Ps[r*36 + i*8 + cc] = p;
            psum += p;
        }
        psum += __shfl_xor_sync(0xffffffffu, psum, 1);
        psum += __shfl_xor_sync(0xffffffffu, psum, 2);
        l = l*scale + psum; m = mnew;
#pragma unroll
        for (int d = 0; d < 16; d++) o[d] *= scale;
        __syncthreads();
#pragma unroll 2
        for (int c = 0; c < 32; c++) {
            float p = Ps[r*36 + c];
            const float* vrow = &Vs[c*68 + (i<<4)];
#pragma unroll
            for (int j = 0; j < 4; j++) {
                float4 v4 = *(const float4*)(vrow + 4*j);
                o[4*j]   += p*v4.x; o[4*j+1] += p*v4.y;
                o[4*j+2] += p*v4.z; o[4*j+3] += p*v4.w;
            }
        }
    }
    float inv = __fdividef(1.f, l);
    float* dst = ao + ((size_t)qg*TB + b)*TE + h*64 + (i<<4);
#pragma unroll
    for (int d = 0; d < 16; d += 4) {
        float4 v; v.x=o[d]*inv; v.y=o[d+1]*inv; v.z=o[d+2]*inv; v.w=o[d+3]*inv;
        *(float4*)(dst + d) = v;
    }
}

template<bool NS>
__global__ void __launch_bounds__(256) add_ln_kernel(
    const float* __restrict__ xa, const float* __restrict__ xb,
    const float* __restrict__ g, const float* __restrict__ bl,
    float* __restrict__ out)
{
    const int t = blockIdx.x, tid = threadIdx.x;
    __shared__ float red[8];
    const size_t base = (size_t)t * TE;
    float v0 = xa[base+tid] + xb[base+tid];
    float v1 = xa[base+tid+256] + xb[base+tid+256];
    float s = v0 + v1;
#pragma unroll
    for (int o = 16; o; o >>= 1) s += __shfl_xor_sync(0xffffffffu, s, o);
    if ((tid & 31) == 0) red[tid>>5] = s;
    __syncthreads();
    if (tid == 0) { float tt=0; for (int w=0;w<8;w++) tt+=red[w]; red[0]=tt; }
    __syncthreads();
    const float mean = red[0] * (1.0f/512.0f);
    __syncthreads();
    float d0 = v0-mean, d1 = v1-mean;
    float q = d0*d0 + d1*d1;
#pragma unroll
    for (int o = 16; o; o >>= 1) q += __shfl_xor_sync(0xffffffffu, q, o);
    if ((tid & 31) == 0) red[tid>>5] = q;
    __syncthreads();
    if (tid == 0) { float tt=0; for (int w=0;w<8;w++) tt+=red[w]; red[0]=tt; }
    __syncthreads();
    const float rs = rsqrtf(red[0]*(1.0f/512.0f) + 1e-5f);
    float o0 = d0*rs*g[tid]     + bl[tid];
    float o1 = d1*rs*g[tid+256] + bl[tid+256];
    if (NS) { o0 = nonsat_f(o0); o1 = nonsat_f(o1); }
    out[base+tid] = o0;
    out[base+tid+256] = o1;
}

// hidden[u,n] = nonsat( x1[perm(u)]@W_w.T + hidden_prev[u]@R_w.T + stack_top[u]@P_w.T + biases )
__global__ void __launch_bounds__(256) hidden_gemm(
    const float* __restrict__ x1, const float* __restrict__ hp,
    const float* __restrict__ sp,
    const float* __restrict__ Ww, const float* __restrict__ Rw, const float* __restrict__ Pw,
    const float* __restrict__ Wb, const float* __restrict__ Rb, const float* __restrict__ Pb,
    float* __restrict__ out)
{
    __shared__ __align__(16) float As[16][68];
    __shared__ __align__(16) float Bs[16][68];
    const int m0 = blockIdx.y * 64, n0 = blockIdx.x * 64;
    const int tid = threadIdx.x;
    const int lr = tid >> 2, lc = (tid & 3) << 2;
    const int tx = tid & 15, ty = tid >> 4;
    const int u = m0 + lr;
    const int tp = ((u & (TS-1)) << 3) | (u >> 10);
    const float* A0 = x1 + (size_t)tp * TE;
    const float* A1 = hp + (size_t)u * TDH - 512;
    const float* A2 = sp + (size_t)u * 4608 - 768;
    const int nr = n0 + lr;
    const float* W0 = Ww + (size_t)nr * TE;
    const float* W1 = Rw + (size_t)nr * TDH - 512;
    const float* W2 = Pw + (size_t)nr * TSW - 768;
    float acc[4][4];
#pragma unroll
    for (int i=0;i<4;i++)
#pragma unroll
        for (int j=0;j<4;j++) acc[i][j]=0.f;
    for (int k0 = 0; k0 < 864; k0 += 16) {
        const int k = k0 + lc;
        const float* ap = (k < 512) ? (A0 + k) : ((k < 768) ? (A1 + k) : (A2 + k));
        const float* wp = (k < 512) ? (W0 + k) : ((k < 768) ? (W1 + k) : (W2 + k));
        float4 av = *(const float4*)ap;
        float4 wv = *(const float4*)wp;
        As[lc+0][lr]=av.x; As[lc+1][lr]=av.y; As[lc+2][lr]=av.z; As[lc+3][lr]=av.w;
        Bs[lc+0][lr]=wv.x; Bs[lc+1][lr]=wv.y; Bs[lc+2][lr]=wv.z; Bs[lc+3][lr]=wv.w;
        __syncthreads();
#pragma unroll
        for (int kk = 0; kk < 16; kk++) {
            float4 a = *(const float4*)&As[kk][ty<<2];
            float4 b = *(const float4*)&Bs[kk][tx<<2];
            float aa[4]={a.x,a.y,a.z,a.w}, bb[4]={b.x,b.y,b.z,b.w};
#pragma unroll
            for (int i=0;i<4;i++)
#pragma unroll
                for (int j=0;j<4;j++) acc[i][j]+=aa[i]*bb[j];
        }
        __syncthreads();
    }
#pragma unroll
    for (int i = 0; i < 4; i++) {
        int uu = m0 + (ty<<2) + i;
        float4 o; float* op=&o.x;
#pragma unroll
        for (int j = 0; j < 4; j++) {
            int nn = n0 + (tx<<2) + j;
            op[j] = nonsat_f(acc[i][j] + Wb[nn] + Rb[nn] + Pb[nn]);
        }
        *(float4*)(out + (size_t)uu*TDH + n0 + (tx<<2)) = o;
    }
}

// logits[t,n] = concat(x1[t], hidden[perm(t)]) @ V_w.T   (N=128, K=768)
__global__ void __launch_bounds__(256) logits_gemm(
    const float* __restrict__ x1, const float* __restrict__ hid,
    const float* __restrict__ Vw, float* __restrict__ out)
{
    __shared__ __align__(16) float As[16][68];
    __shared__ __align__(16) float Bs[16][68];
    const int m0 = blockIdx.y * 64, n0 = blockIdx.x * 64;
    const int tid = threadIdx.x;
    const int lr = tid >> 2, lc = (tid & 3) << 2;
    const int tx = tid & 15, ty = tid >> 4;
    const int t = m0 + lr;
    const int up = ((t & 7) << 10) | (t >> 3);
    const float* A0 = x1 + (size_t)t * TE;
    const float* A1 = hid + (size_t)up * TDH - 512;
    const float* Wp = Vw + (size_t)(n0 + lr) * 768 + lc;
    float acc[4][4];
#pragma unroll
    for (int i=0;i<4;i++)
#pragma unroll
        for (int j=0;j<4;j++) acc[i][j]=0.f;
    for (int k0 = 0; k0 < 768; k0 += 16) {
        const int k = k0 + lc;
        const float* ap = (k < 512) ? (A0 + k) : (A1 + k);
        float4 av = *(const float4*)ap;
        float4 wv = *(const float4*)(Wp + k0);
        As[lc+0][lr]=av.x; As[lc+1][lr]=av.y; As[lc+2][lr]=av.z; As[lc+3][lr]=av.w;
        Bs[lc+0][lr]=wv.x; Bs[lc+1][lr]=wv.y; Bs[lc+2][lr]=wv.z; Bs[lc+3][lr]=wv.w;
        __syncthreads();
#pragma unroll
        for (int kk = 0; kk < 16; kk++) {
            float4 a = *(const float4*)&As[kk][ty<<2];
            float4 b = *(const float4*)&Bs[kk][tx<<2];
            float aa[4]={a.x,a.y,a.z,a.w}, bb[4]={b.x,b.y,b.z,b.w};
#pragma unroll
            for (int i=0;i<4;i++)
#pragma unroll
                for (int j=0;j<4;j++) acc[i][j]+=aa[i]*bb[j];
        }
        __syncthreads();
    }
#pragma unroll
    for (int i = 0; i < 4; i++) {
        int m = m0 + (ty<<2) + i;
        float4 o; o.x=acc[i][0]; o.y=acc[i][1]; o.z=acc[i][2]; o.w=acc[i][3];
        *(float4*)(out + (size_t)m*128 + n0 + (tx<<2)) = o;
    }
}

__global__ void __launch_bounds__(256) softmax128_kernel(float* __restrict__ lg)
{
    const int t = blockIdx.x * 8 + (threadIdx.x >> 5);
    const int lane = threadIdx.x & 31;
    float4* p = (float4*)(lg + (size_t)t * 128) + lane;
    float4 v = *p;
    float mx = fmaxf(fmaxf(v.x, v.y), fmaxf(v.z, v.w));
#pragma unroll
    for (int o = 16; o; o >>= 1) mx = fmaxf(mx, __shfl_xor_sync(0xffffffffu, mx, o));
    v.x = __expf(v.x-mx); v.y = __expf(v.y-mx); v.z = __expf(v.z-mx); v.w = __expf(v.w-mx);
    float s = v.x + v.y + v.z + v.w;
#pragma unroll
    for (int o = 16; o; o >>= 1) s += __shfl_xor_sync(0xffffffffu, s, o);
    float is = __fdividef(1.f, s);
    v.x *= is; v.y *= is; v.z *= is; v.w *= is;
    *p = v;
}

__global__ void __launch_bounds__(128) stack_kernel(
    const float* __restrict__ hidden, const float* __restrict__ sp,
    const float* __restrict__ Aw, const float* __restrict__ Ab,
    const float* __restrict__ Dw, const float* __restrict__ Db,
    float* __restrict__ out)
{
    __shared__ __align__(16) float h[256];
    __shared__ __align__(16) float inp[96];
    __shared__ float ctl[3];
    const int u = blockIdx.x, tid = threadIdx.x;
    const float* hrow = hidden + (size_t)u * 256;
    h[tid] = hrow[tid]; h[tid+128] = hrow[tid+128];
    __syncthreads();
    if (tid < 96) {
        const float* w = Dw + tid * 256;
        float s = Db[tid];
        for (int k = 0; k < 256; k += 4) {
            float4 wv = *(const float4*)(w + k);
            s += wv.x*h[k] + wv.y*h[k+1] + wv.z*h[k+2] + wv.w*h[k+3];
        }
        inp[tid] = nonsat_f(s);
    } else if (tid < 99) {
        int i = tid - 96;
        const float* w = Aw + i * 256;
        float s = Ab[i];
        for (int k = 0; k < 256; k++) s += w[k]*h[k];
        ctl[i] = s;
    }
    __syncthreads();
    float mx = fmaxf(ctl[0], fmaxf(ctl[1], ctl[2]));
    float e0 = __expf(ctl[0]-mx), e1 = __expf(ctl[1]-mx), e2 = __expf(ctl[2]-mx);
    float is = __fdividef(1.f, e0+e1+e2);
    float c0 = e0*is, c1 = e1*is, c2 = e2*is;
    const float4* prev = (const float4*)(sp + (size_t)u * 4608);
    float4* dst = (float4*)(out + (size_t)u * 4608);
    const float4* inp4 = (const float4*)inp;
    for (int idx = tid; idx < 1152; idx += 128) {
        int d = idx / 24;
        float4 p = prev[idx];
        float4 up = (d == 0) ? inp4[idx] : prev[idx-24];
        float4 dn;
        if (d == 47) { dn.x=dn.y=dn.z=dn.w=0.f; } else dn = prev[idx+24];
        float4 o;
        o.x = c2*p.x + c0*up.x + c1*dn.x;
        o.y = c2*p.y + c0*up.y + c1*dn.y;
        o.z = c2*p.z + c0*up.z + c1*dn.z;
        o.w = c2*p.w + c0*up.w + c1*dn.w;
        dst[idx] = o;
    }
}

extern "C" void kernel_launch(void* const* d_in, const int* in_sizes, int n_in,
                              void* d_out, int out_size) {
    const float* x_in = (const float*)d_in[0];
    const float* hidden_prev = (const float*)d_in[1];
    const float* stack_prev  = (const float*)d_in[2];
    const float* in_proj_w = (const float*)d_in[3];
    const float* in_proj_b = (const float*)d_in[4];
    const float* out_proj_w = (const float*)d_in[5];
    const float* out_proj_b = (const float*)d_in[6];
    const float* ln1_g = (const float*)d_in[7];
    const float* ln1_b = (const float*)d_in[8];
    const float* ln2_g = (const float*)d_in[9];
    const float* ln2_b = (const float*)d_in[10];
    const float* W_w = (const float*)d_in[11];
    const float* W_b = (const float*)d_in[12];
    const float* R_w = (const float*)d_in[13];
    const float* R_b = (const float*)d_in[14];
    const float* P_w = (const float*)d_in[15];
    const float* P_b = (const float*)d_in[16];
    const float* V_w = (const float*)d_in[17];
    const float* U_w = (const float*)d_in[18];
    const float* A_w = (const float*)d_in[19];
    const float* A_b = (const float*)d_in[20];
    const float* D_w = (const float*)d_in[21];
    const float* D_b = (const float*)d_in[22];
    const float* ffi_w = (const float*)d_in[23];
    const float* ffi_b = (const float*)d_in[24];
    const float* ffo_w = (const float*)d_in[25];
    const float* ffo_b = (const float*)d_in[26];

    static float *p_qkv=nullptr,*p_ao,*p_proj,*p_x1,*p_lg,*p_x2,*p_ffh,*p_ffo;
    if (!p_qkv) {
        cudaGetSymbolAddress((void**)&p_qkv,  g_qkv);
        cudaGetSymbolAddress((void**)&p_ao,   g_ao);
        cudaGetSymbolAddress((void**)&p_proj, g_proj);
        cudaGetSymbolAddress((void**)&p_x1,   g_x1);
        cudaGetSymbolAddress((void**)&p_lg,   g_lg);
        cudaGetSymbolAddress((void**)&p_x2,   g_x2);
        cudaGetSymbolAddress((void**)&p_ffh,  g_ffh);
        cudaGetSymbolAddress((void**)&p_ffo,  g_ffo);
    }

    float* out_x = (float*)d_out;
    float* out_hidden = out_x + (size_t)NTOK * TE;
    float* out_stack  = out_hidden + (size_t)NTOK * TDH;

    // 1) qkv = x_in @ in_proj_w.T + b
    gemm64<0><<<dim3(24,128),256>>>(x_in, in_proj_w, in_proj_b, nullptr, p_qkv, NTOK, 1536, 512);
    // 2) fused causal attention
    attn_kernel<<<dim3(16,64),256>>>(p_qkv, p_ao);
    // 3) out projection
    gemm64<0><<<dim3(8,128),256>>>(p_ao, out_proj_w, out_proj_b, nullptr, p_proj, NTOK, 512, 512);
    // 4) x1 = nonsat(LN(x_in + proj))
    add_ln_kernel<true><<<NTOK,256>>>(x_in, p_proj, ln1_g, ln1_b, p_x1);
    // 5) hidden (written straight to output)
    hidden_gemm<<<dim3(4,128),256>>>(p_x1, hidden_prev, stack_prev,
                                     W_w, R_w, P_w, W_b, R_b, P_b, out_hidden);
    // 6) logits = concat(x1, hidden_perm) @ V_w.T
    logits_gemm<<<dim3(2,128),256>>>(p_x1, out_hidden, V_w, p_lg);
    // 7) softmax over 128
    softmax128_kernel<<<NTOK/8,256>>>(p_lg);
    // 8) x2 = 0.5*(x1 + sm @ U_w.T)
    gemm64<2><<<dim3(8,128),256>>>(p_lg, U_w, nullptr, p_x1, p_x2, NTOK, 512, 128);
    // 9) stack update (written straight to output)
    stack_kernel<<<NTOK,128>>>(out_hidden, stack_prev, A_w, A_b, D_w, D_b, out_stack);
    // 10) ff hidden = nonsat(x2 @ ffi_w.T + b)
    gemm64<1><<<dim3(32,128),256>>>(p_x2, ffi_w, ffi_b, nullptr, p_ffh, NTOK, 2048, 512);
    // 11) ff out
    gemm64<0><<<dim3(8,128),256>>>(p_ffh, ffo_w, ffo_b, nullptr, p_ffo, NTOK, 512, 2048);
    // 12) x_out = LN(x2 + ff)
    add_ln_kernel<false><<<NTOK,256>>>(p_x2, p_ffo, ln2_g, ln2_b, out_x);
}

// round 5
// speedup vs baseline: 1.2372x; 1.2372x over previous
#include <cuda_runtime.h>
#include <cuda_bf16.h>
#include <math.h>
#include <stdint.h>

#define TS 1024
#define TB 8
#define TE 512
#define TDH 256
#define TSW 96
#define NTOK 8192

// ---------------- fp32 scratch ----------------
__device__ __align__(16) float g_qkv [(size_t)NTOK*1536];
__device__ __align__(16) float g_ao  [(size_t)NTOK*TE];
__device__ __align__(16) float g_proj[(size_t)NTOK*TE];
__device__ __align__(16) float g_x1  [(size_t)NTOK*TE];
__device__ __align__(16) float g_lg  [(size_t)NTOK*128];
__device__ __align__(16) float g_x2  [(size_t)NTOK*TE];
__device__ __align__(16) float g_ffh [(size_t)NTOK*2048];
__device__ __align__(16) float g_ffo [(size_t)NTOK*TE];

// ---------------- bf16 split scratch (hi/lo) ----------------
__device__ __align__(16) __nv_bfloat16 b_xin[2][(size_t)NTOK*512];
__device__ __align__(16) __nv_bfloat16 b_ao [2][(size_t)NTOK*512];
__device__ __align__(16) __nv_bfloat16 b_lg [2][(size_t)NTOK*128];
__device__ __align__(16) __nv_bfloat16 b_x2 [2][(size_t)NTOK*512];
__device__ __align__(16) __nv_bfloat16 b_ffh[2][(size_t)NTOK*2048];
__device__ __align__(16) __nv_bfloat16 b_w1 [2][1536*512];
__device__ __align__(16) __nv_bfloat16 b_w2 [2][512*512];
__device__ __align__(16) __nv_bfloat16 b_uw [2][512*128];
__device__ __align__(16) __nv_bfloat16 b_w3 [2][2048*512];
__device__ __align__(16) __nv_bfloat16 b_w4 [2][512*2048];

__device__ __forceinline__ float nonsat_f(float x) {
    float y = x;
#pragma unroll 1
    for (int it = 0; it < 32; ++it) {
        float y2 = y * y;
        float yn = __fdividef(0.66666668f * y * y2 + x, y2 + 1.0f);
        float d = fabsf(yn - y);
        y = yn;
        if (d <= 1e-6f) break;
    }
    return y;
}

// ---------------- fp32 -> (bf16 hi, bf16 lo) split ----------------
__global__ void __launch_bounds__(256) split_kernel(
    const float* __restrict__ src, __nv_bfloat16* __restrict__ hi,
    __nv_bfloat16* __restrict__ lo, int n4)
{
    int i = blockIdx.x * 256 + threadIdx.x;
    if (i >= n4) return;
    float4 v = ((const float4*)src)[i];
    union { __nv_bfloat16 b[4]; uint2 u; } H, L;
    H.b[0] = __float2bfloat16(v.x); L.b[0] = __float2bfloat16(v.x - __bfloat162float(H.b[0]));
    H.b[1] = __float2bfloat16(v.y); L.b[1] = __float2bfloat16(v.y - __bfloat162float(H.b[1]));
    H.b[2] = __float2bfloat16(v.z); L.b[2] = __float2bfloat16(v.z - __bfloat162float(H.b[2]));
    H.b[3] = __float2bfloat16(v.w); L.b[3] = __float2bfloat16(v.w - __bfloat162float(H.b[3]));
    ((uint2*)hi)[i] = H.u;
    ((uint2*)lo)[i] = L.u;
}

// ---------------- HMMA (mma.sync bf16) split GEMM ----------------
// C(MxN) = A(MxK) @ W(NxK)^T via Ah*Wh + Ah*Wl + Al*Wh, fp32 accum
// CTA tile 128x128, 8 warps (2 row-groups x 4 col-groups), warp tile 64x32.
// EPI 0:+bias  1:nonsat(+bias)  2:0.5*(acc+res)
#define T_AH 0
#define T_AL 16384
#define T_BH 32768
#define T_BL 49152
#define T_SMEM 65536

__device__ __forceinline__ uint32_t lds_bf2(const char* smem, int tile, int r, int k) {
    uint32_t o = (uint32_t)(r * 128 + k * 2);
    o ^= (o >> 3) & 0x70;
    return *(const uint32_t*)(smem + tile + o);
}
__device__ __forceinline__ void mma16816(float* c, const uint32_t* a, const uint32_t* b) {
    asm volatile(
        "mma.sync.aligned.m16n8k16.row.col.f32.bf16.bf16.f32 "
        "{%0,%1,%2,%3}, {%4,%5,%6,%7}, {%8,%9}, {%0,%1,%2,%3};\n"
        : "+f"(c[0]), "+f"(c[1]), "+f"(c[2]), "+f"(c[3])
        : "r"(a[0]), "r"(a[1]), "r"(a[2]), "r"(a[3]), "r"(b[0]), "r"(b[1]));
}

template<int EPI>
__global__ void __launch_bounds__(256) tgemm(
    const __nv_bfloat16* __restrict__ Ah, const __nv_bfloat16* __restrict__ Al,
    const __nv_bfloat16* __restrict__ Wh, const __nv_bfloat16* __restrict__ Wl,
    const float* __restrict__ bias, const float* __restrict__ res,
    float* __restrict__ C, int M, int N, int K)
{
    extern __shared__ char smem[];
    const int tid = threadIdx.x, wid = tid >> 5, lane = tid & 31;
    const int m0 = blockIdx.y * 128, n0 = blockIdx.x * 128;
    const int g = lane >> 2, t2 = (lane & 3) << 1;
    const int wr = (wid & 1) << 6;     // warp row base within tile (0/64)
    const int wc = (wid >> 1) << 5;    // warp col base within tile (0..96)

    float c[4][4][4];
#pragma unroll
    for (int i = 0; i < 4; i++)
#pragma unroll
        for (int j = 0; j < 4; j++)
#pragma unroll
            for (int q = 0; q < 4; q++) c[i][j][q] = 0.f;

    const int nch = K >> 6;
    for (int ch = 0; ch < nch; ch++) {
        const int k0 = ch << 6;
        // load 4 tiles of 128x64 bf16 (SW128 swizzled)
#pragma unroll
        for (int t = 0; t < 4; t++) {
            int e = tid + (t << 8);
            int r = e >> 3, q = e & 7;
            uint32_t off = (uint32_t)((r << 7) + (q << 4));
            off ^= (off >> 3) & 0x70;
            const size_t ga = (size_t)(m0 + r) * K + k0 + (q << 3);
            const size_t gb = (size_t)(n0 + r) * K + k0 + (q << 3);
            *(uint4*)(smem + T_AH + off) = *(const uint4*)(Ah + ga);
            *(uint4*)(smem + T_AL + off) = *(const uint4*)(Al + ga);
            *(uint4*)(smem + T_BH + off) = *(const uint4*)(Wh + gb);
            *(uint4*)(smem + T_BL + off) = *(const uint4*)(Wl + gb);
        }
        __syncthreads();
#pragma unroll
        for (int kk = 0; kk < 64; kk += 16) {
            uint32_t ah[4][4], al[4][4], bh[4][2], bl[4][2];
#pragma unroll
            for (int mi = 0; mi < 4; mi++) {
                int r0 = wr + (mi << 4) + g;
                ah[mi][0] = lds_bf2(smem, T_AH, r0,     kk + t2);
                ah[mi][1] = lds_bf2(smem, T_AH, r0 + 8, kk + t2);
                ah[mi][2] = lds_bf2(smem, T_AH, r0,     kk + t2 + 8);
                ah[mi][3] = lds_bf2(smem, T_AH, r0 + 8, kk + t2 + 8);
                al[mi][0] = lds_bf2(smem, T_AL, r0,     kk + t2);
                al[mi][1] = lds_bf2(smem, T_AL, r0 + 8, kk + t2);
                al[mi][2] = lds_bf2(smem, T_AL, r0,     kk + t2 + 8);
                al[mi][3] = lds_bf2(smem, T_AL, r0 + 8, kk + t2 + 8);
            }
#pragma unroll
            for (int ni = 0; ni < 4; ni++) {
                int nr = wc + (ni << 3) + g;
                bh[ni][0] = lds_bf2(smem, T_BH, nr, kk + t2);
                bh[ni][1] = lds_bf2(smem, T_BH, nr, kk + t2 + 8);
                bl[ni][0] = lds_bf2(smem, T_BL, nr, kk + t2);
                bl[ni][1] = lds_bf2(smem, T_BL, nr, kk + t2 + 8);
            }
#pragma unroll
            for (int mi = 0; mi < 4; mi++)
#pragma unroll
                for (int ni = 0; ni < 4; ni++) {
                    mma16816(c[mi][ni], ah[mi], bh[ni]);
                    mma16816(c[mi][ni], ah[mi], bl[ni]);
                    mma16816(c[mi][ni], al[mi], bh[ni]);
                }
        }
        __syncthreads();
    }

    // epilogue
#pragma unroll
    for (int mi = 0; mi < 4; mi++) {
#pragma unroll
        for (int ni = 0; ni < 4; ni++) {
            int row = m0 + wr + (mi << 4) + g;
            int col = n0 + wc + (ni << 3) + t2;
#pragma unroll
            for (int h = 0; h < 2; h++) {
                int rr = row + h * 8;
                float v0 = c[mi][ni][2 * h], v1 = c[mi][ni][2 * h + 1];
                float2 o;
                if (EPI == 0) {
                    o.x = v0 + bias[col]; o.y = v1 + bias[col + 1];
                } else if (EPI == 1) {
                    o.x = nonsat_f(v0 + bias[col]); o.y = nonsat_f(v1 + bias[col + 1]);
                } else {
                    const float2 rv = *(const float2*)(res + (size_t)rr * N + col);
                    o.x = 0.5f * (v0 + rv.x); o.y = 0.5f * (v1 + rv.y);
                }
                *(float2*)(C + (size_t)rr * N + col) = o;
            }
        }
    }
}

// ---------------- fp32 fused causal attention ----------------
__global__ void __launch_bounds__(256) attn_kernel(const float* __restrict__ qkv,
                                                   float* __restrict__ ao)
{
    __shared__ __align__(16) float Qs[64*68];
    __shared__ __align__(16) float Ks[32*68];
    __shared__ __align__(16) float Vs[32*68];
    __shared__ __align__(16) float Ps[64*36];
    const int q0 = blockIdx.x * 64;
    const int b  = blockIdx.y >> 3, h = blockIdx.y & 7;
    const int tid = threadIdx.x;
    const int r = tid >> 2, i = tid & 3;
    const int qg = q0 + r;
    {
        const float* src = qkv + ((size_t)qg*TB + b)*1536 + h*64 + (i<<4);
#pragma unroll
        for (int j = 0; j < 16; j += 4) {
            float4 v = *(const float4*)(src + j);
            Qs[r*68+(i<<4)+j]=v.x; Qs[r*68+(i<<4)+j+1]=v.y;
            Qs[r*68+(i<<4)+j+2]=v.z; Qs[r*68+(i<<4)+j+3]=v.w;
        }
    }
    float o[16];
#pragma unroll
    for (int d = 0; d < 16; d++) o[d] = 0.f;
    float m = -1e30f, l = 0.f;
    const int ntiles = (q0 >> 5) + 2;
    for (int kt = 0; kt < ntiles; kt++) {
        const int k0 = kt << 5;
        __syncthreads();
#pragma unroll
        for (int u2 = 0; u2 < 2; u2++) {
            int e4 = tid + (u2<<8);
            int kr = e4 >> 4, kc = (e4 & 15) << 2;
            const float* rowp = qkv + ((size_t)(k0+kr)*TB + b)*1536 + h*64;
            float4 kv = *(const float4*)(rowp + 512 + kc);
            float4 vv = *(const float4*)(rowp + 1024 + kc);
            Ks[kr*68+kc]=kv.x; Ks[kr*68+kc+1]=kv.y; Ks[kr*68+kc+2]=kv.z; Ks[kr*68+kc+3]=kv.w;
            Vs[kr*68+kc]=vv.x; Vs[kr*68+kc+1]=vv.y; Vs[kr*68+kc+2]=vv.z; Vs[kr*68+kc+3]=vv.w;
        }
        __syncthreads();
        float sc[8];
#pragma unroll
        for (int cc = 0; cc < 8; cc++) sc[cc] = 0.f;
#pragma unroll
        for (int kk = 0; kk < 64; kk += 4) {
            float4 q4 = *(const float4*)&Qs[r*68+kk];
#pragma unroll
            for (int cc = 0; cc < 8; cc++) {
                float4 k4 = *(const float4*)&Ks[(i*8+cc)*68+kk];
                sc[cc] += q4.x*k4.x + q4.y*k4.y + q4.z*k4.z + q4.w*k4.w;
            }
        }
        float tmax = -1e30f;
#pragma unroll
        for (int cc = 0; cc < 8; cc++) {
            sc[cc] = (k0 + i*8 + cc <= qg) ? sc[cc]*0.125f : -1e30f;
            tmax = fmaxf(tmax, sc[cc]);
        }
        tmax = fmaxf(tmax, __shfl_xor_sync(0xffffffffu, tmax, 1));
        tmax = fmaxf(tmax, __shfl_xor_sync(0xffffffffu, tmax, 2));
        float mnew = fmaxf(m, tmax);
        float scale = __expf(m - mnew);
        float psum = 0.f;
#pragma unroll
        for (int cc = 0; cc < 8; cc++) {
            float p = __expf(sc[cc] - mnew);
            Ps[r*36 + i*8 + cc] = p;
            psum += p;
        }
        psum += __shfl_xor_sync(0xffffffffu, psum, 1);
        psum += __shfl_xor_sync(0xffffffffu, psum, 2);
        l = l*scale + psum; m = mnew;
#pragma unroll
        for (int d = 0; d < 16; d++) o[d] *= scale;
        __syncthreads();
#pragma unroll 2
        for (int c = 0; c < 32; c++) {
            float p = Ps[r*36 + c];
            const float* vrow = &Vs[c*68 + (i<<4)];
#pragma unroll
            for (int j = 0; j < 4; j++) {
                float4 v4 = *(const float4*)(vrow + 4*j);
                o[4*j]   += p*v4.x; o[4*j+1] += p*v4.y;
                o[4*j+2] += p*v4.z; o[4*j+3] += p*v4.w;
            }
        }
    }
    float inv = __fdividef(1.f, l);
    float* dst = ao + ((size_t)qg*TB + b)*TE + h*64 + (i<<4);
#pragma unroll
    for (int d = 0; d < 16; d += 4) {
        float4 v; v.x=o[d]*inv; v.y=o[d+1]*inv; v.z=o[d+2]*inv; v.w=o[d+3]*inv;
        *(float4*)(dst + d) = v;
    }
}

template<bool NS>
__global__ void __launch_bounds__(256) add_ln_kernel(
    const float* __restrict__ xa, const float* __restrict__ xb,
    const float* __restrict__ g, const float* __restrict__ bl,
    float* __restrict__ out)
{
    const int t = blockIdx.x, tid = threadIdx.x;
    __shared__ float red[8];
    const size_t base = (size_t)t * TE;
    float v0 = xa[base+tid] + xb[base+tid];
    float v1 = xa[base+tid+256] + xb[base+tid+256];
    float s = v0 + v1;
#pragma unroll
    for (int o = 16; o; o >>= 1) s += __shfl_xor_sync(0xffffffffu, s, o);
    if ((tid & 31) == 0) red[tid>>5] = s;
    __syncthreads();
    if (tid == 0) { float tt=0; for (int w=0;w<8;w++) tt+=red[w]; red[0]=tt; }
    __syncthreads();
    const float mean = red[0] * (1.0f/512.0f);
    __syncthreads();
    float d0 = v0-mean, d1 = v1-mean;
    float q = d0*d0 + d1*d1;
#pragma unroll
    for (int o = 16; o; o >>= 1) q += __shfl_xor_sync(0xffffffffu, q, o);
    if ((tid & 31) == 0) red[tid>>5] = q;
    __syncthreads();
    if (tid == 0) { float tt=0; for (int w=0;w<8;w++) tt+=red[w]; red[0]=tt; }
    __syncthreads();
    const float rs = rsqrtf(red[0]*(1.0f/512.0f) + 1e-5f);
    float o0 = d0*rs*g[tid]     + bl[tid];
    float o1 = d1*rs*g[tid+256] + bl[tid+256];
    if (NS) { o0 = nonsat_f(o0); o1 = nonsat_f(o1); }
    out[base+tid] = o0;
    out[base+tid+256] = o1;
}

__global__ void __launch_bounds__(256) hidden_gemm(
    const float* __restrict__ x1, const float* __restrict__ hp,
    const float* __restrict__ sp,
    const float* __restrict__ Ww, const float* __restrict__ Rw, const float* __restrict__ Pw,
    const float* __restrict__ Wb, const float* __restrict__ Rb, const float* __restrict__ Pb,
    float* __restrict__ out)
{
    __shared__ __align__(16) float As[16][68];
    __shared__ __align__(16) float Bs[16][68];
    const int m0 = blockIdx.y * 64, n0 = blockIdx.x * 64;
    const int tid = threadIdx.x;
    const int lr = tid >> 2, lc = (tid & 3) << 2;
    const int tx = tid & 15, ty = tid >> 4;
    const int u = m0 + lr;
    const int tp = ((u & (TS-1)) << 3) | (u >> 10);
    const float* A0 = x1 + (size_t)tp * TE;
    const float* A1 = hp + (size_t)u * TDH - 512;
    const float* A2 = sp + (size_t)u * 4608 - 768;
    const int nr = n0 + lr;
    const float* W0 = Ww + (size_t)nr * TE;
    const float* W1 = Rw + (size_t)nr * TDH - 512;
    const float* W2 = Pw + (size_t)nr * TSW - 768;
    float acc[4][4];
#pragma unroll
    for (int i=0;i<4;i++)
#pragma unroll
        for (int j=0;j<4;j++) acc[i][j]=0.f;
    for (int k0 = 0; k0 < 864; k0 += 16) {
        const int k = k0 + lc;
        const float* ap = (k < 512) ? (A0 + k) : ((k < 768) ? (A1 + k) : (A2 + k));
        const float* wp = (k < 512) ? (W0 + k) : ((k < 768) ? (W1 + k) : (W2 + k));
        float4 av = *(const float4*)ap;
        float4 wv = *(const float4*)wp;
        As[lc+0][lr]=av.x; As[lc+1][lr]=av.y; As[lc+2][lr]=av.z; As[lc+3][lr]=av.w;
        Bs[lc+0][lr]=wv.x; Bs[lc+1][lr]=wv.y; Bs[lc+2][lr]=wv.z; Bs[lc+3][lr]=wv.w;
        __syncthreads();
#pragma unroll
        for (int kk = 0; kk < 16; kk++) {
            float4 a = *(const float4*)&As[kk][ty<<2];
            float4 b = *(const float4*)&Bs[kk][tx<<2];
            float aa[4]={a.x,a.y,a.z,a.w}, bb[4]={b.x,b.y,b.z,b.w};
#pragma unroll
            for (int i=0;i<4;i++)
#pragma unroll
                for (int j=0;j<4;j++) acc[i][j]+=aa[i]*bb[j];
        }
        __syncthreads();
    }
#pragma unroll
    for (int i = 0; i < 4; i++) {
        int uu = m0 + (ty<<2) + i;
        float4 o; float* op=&o.x;
#pragma unroll
        for (int j = 0; j < 4; j++) {
            int nn = n0 + (tx<<2) + j;
            op[j] = nonsat_f(acc[i][j] + Wb[nn] + Rb[nn] + Pb[nn]);
        }
        *(float4*)(out + (size_t)uu*TDH + n0 + (tx<<2)) = o;
    }
}

__global__ void __launch_bounds__(256) logits_gemm(
    const float* __restrict__ x1, const float* __restrict__ hid,
    const float* __restrict__ Vw, float* __restrict__ out)
{
    __shared__ __align__(16) float As[16][68];
    __shared__ __align__(16) float Bs[16][68];
    const int m0 = blockIdx.y * 64, n0 = blockIdx.x * 64;
    const int tid = threadIdx.x;
    const int lr = tid >> 2, lc = (tid & 3) << 2;
    const int tx = tid & 15, ty = tid >> 4;
    const int t = m0 + lr;
    const int up = ((t & 7) << 10) | (t >> 3);
    const float* A0 = x1 + (size_t)t * TE;
    const float* A1 = hid + (size_t)up * TDH - 512;
    const float* Wp = Vw + (size_t)(n0 + lr) * 768 + lc;
    float acc[4][4];
#pragma unroll
    for (int i=0;i<4;i++)
#pragma unroll
        for (int j=0;j<4;j++) acc[i][j]=0.f;
    for (int k0 = 0; k0 < 768; k0 += 16) {
        const int k = k0 + lc;
        const float* ap = (k < 512) ? (A0 + k) : (A1 + k);
        float4 av = *(const float4*)ap;
        float4 wv = *(const float4*)(Wp + k0);
        As[lc+0][lr]=av.x; As[lc+1][lr]=av.y; As[lc+2][lr]=av.z; As[lc+3][lr]=av.w;
        Bs[lc+0][lr]=wv.x; Bs[lc+1][lr]=wv.y; Bs[lc+2][lr]=wv.z; Bs[lc+3][lr]=wv.w;
        __syncthreads();
#pragma unroll
        for (int kk = 0; kk < 16; kk++) {
            float4 a = *(const float4*)&As[kk][ty<<2];
            float4 b = *(const float4*)&Bs[kk][tx<<2];
            float aa[4]={a.x,a.y,a.z,a.w}, bb[4]={b.x,b.y,b.z,b.w};
#pragma unroll
            for (int i=0;i<4;i++)
#pragma unroll
                for (int j=0;j<4;j++) acc[i][j]+=aa[i]*bb[j];
        }
        __syncthreads();
    }
#pragma unroll
    for (int i = 0; i < 4; i++) {
        int m = m0 + (ty<<2) + i;
        float4 o; o.x=acc[i][0]; o.y=acc[i][1]; o.z=acc[i][2]; o.w=acc[i][3];
        *(float4*)(out + (size_t)m*128 + n0 + (tx<<2)) = o;
    }
}

__global__ void __launch_bounds__(256) softmax128_kernel(float* __restrict__ lg)
{
    const int t = blockIdx.x * 8 + (threadIdx.x >> 5);
    const int lane = threadIdx.x & 31;
    float4* p = (float4*)(lg + (size_t)t * 128) + lane;
    float4 v = *p;
    float mx = fmaxf(fmaxf(v.x, v.y), fmaxf(v.z, v.w));
#pragma unroll
    for (int o = 16; o; o >>= 1) mx = fmaxf(mx, __shfl_xor_sync(0xffffffffu, mx, o));
    v.x = __expf(v.x-mx); v.y = __expf(v.y-mx); v.z = __expf(v.z-mx); v.w = __expf(v.w-mx);
    float s = v.x + v.y + v.z + v.w;
#pragma unroll
    for (int o = 16; o; o >>= 1) s += __shfl_xor_sync(0xffffffffu, s, o);
    float is = __fdividef(1.f, s);
    v.x *= is; v.y *= is; v.z *= is; v.w *= is;
    *p = v;
}

__global__ void __launch_bounds__(128) stack_kernel(
    const float* __restrict__ hidden, const float* __restrict__ sp,
    const float* __restrict__ Aw, const float* __restrict__ Ab,
    const float* __restrict__ Dw, const float* __restrict__ Db,
    float* __restrict__ out)
{
    __shared__ __align__(16) float h[256];
    __shared__ __align__(16) float inp[96];
    __shared__ float ctl[3];
    const int u = blockIdx.x, tid = threadIdx.x;
    const float* hrow = hidden + (size_t)u * 256;
    h[tid] = hrow[tid]; h[tid+128] = hrow[tid+128];
    __syncthreads();
    if (tid < 96) {
        const float* w = Dw + tid * 256;
        float s = Db[tid];
        for (int k = 0; k < 256; k += 4) {
            float4 wv = *(const float4*)(w + k);
            s += wv.x*h[k] + wv.y*h[k+1] + wv.z*h[k+2] + wv.w*h[k+3];
        }
        inp[tid] = nonsat_f(s);
    } else if (tid < 99) {
        int i = tid - 96;
        const float* w = Aw + i * 256;
        float s = Ab[i];
        for (int k = 0; k < 256; k++) s += w[k]*h[k];
        ctl[i] = s;
    }
    __syncthreads();
    float mx = fmaxf(ctl[0], fmaxf(ctl[1], ctl[2]));
    float e0 = __expf(ctl[0]-mx), e1 = __expf(ctl[1]-mx), e2 = __expf(ctl[2]-mx);
    float is = __fdividef(1.f, e0+e1+e2);
    float c0 = e0*is, c1 = e1*is, c2 = e2*is;
    const float4* prev = (const float4*)(sp + (size_t)u * 4608);
    float4* dst = (float4*)(out + (size_t)u * 4608);
    const float4* inp4 = (const float4*)inp;
    for (int idx = tid; idx < 1152; idx += 128) {
        int d = idx / 24;
        float4 p = prev[idx];
        float4 up = (d == 0) ? inp4[idx] : prev[idx-24];
        float4 dn;
        if (d == 47) { dn.x=dn.y=dn.z=dn.w=0.f; } else dn = prev[idx+24];
        float4 o;
        o.x = c2*p.x + c0*up.x + c1*dn.x;
        o.y = c2*p.y + c0*up.y + c1*dn.y;
        o.z = c2*p.z + c0*up.z + c1*dn.z;
        o.w = c2*p.w + c0*up.w + c1*dn.w;
        dst[idx] = o;
    }
}

static inline void split_launch(const float* src, __nv_bfloat16* hi, __nv_bfloat16* lo, size_t n) {
    int n4 = (int)(n >> 2);
    split_kernel<<<(n4 + 255) / 256, 256>>>(src, hi, lo, n4);
}

extern "C" void kernel_launch(void* const* d_in, const int* in_sizes, int n_in,
                              void* d_out, int out_size) {
    const float* x_in = (const float*)d_in[0];
    const float* hidden_prev = (const float*)d_in[1];
    const float* stack_prev  = (const float*)d_in[2];
    const float* in_proj_w = (const float*)d_in[3];
    const float* in_proj_b = (const float*)d_in[4];
    const float* out_proj_w = (const float*)d_in[5];
    const float* out_proj_b = (const float*)d_in[6];
    const float* ln1_g = (const float*)d_in[7];
    const float* ln1_b = (const float*)d_in[8];
    const float* ln2_g = (const float*)d_in[9];
    const float* ln2_b = (const float*)d_in[10];
    const float* W_w = (const float*)d_in[11];
    const float* W_b = (const float*)d_in[12];
    const float* R_w = (const float*)d_in[13];
    const float* R_b = (const float*)d_in[14];
    const float* P_w = (const float*)d_in[15];
    const float* P_b = (const float*)d_in[16];
    const float* V_w = (const float*)d_in[17];
    const float* U_w = (const float*)d_in[18];
    const float* A_w = (const float*)d_in[19];
    const float* A_b = (const float*)d_in[20];
    const float* D_w = (const float*)d_in[21];
    const float* D_b = (const float*)d_in[22];
    const float* ffi_w = (const float*)d_in[23];
    const float* ffi_b = (const float*)d_in[24];
    const float* ffo_w = (const float*)d_in[25];
    const float* ffo_b = (const float*)d_in[26];

    static bool init_done = false;
    static float *p_qkv,*p_ao,*p_proj,*p_x1,*p_lg,*p_x2,*p_ffh,*p_ffo;
    static __nv_bfloat16 *pb_xin[2],*pb_ao[2],*pb_lg[2],*pb_x2[2],*pb_ffh[2];
    static __nv_bfloat16 *pb_w1[2],*pb_w2[2],*pb_uw[2],*pb_w3[2],*pb_w4[2];
    if (!init_done) {
        cudaGetSymbolAddress((void**)&p_qkv,  g_qkv);
        cudaGetSymbolAddress((void**)&p_ao,   g_ao);
        cudaGetSymbolAddress((void**)&p_proj, g_proj);
        cudaGetSymbolAddress((void**)&p_x1,   g_x1);
        cudaGetSymbolAddress((void**)&p_lg,   g_lg);
        cudaGetSymbolAddress((void**)&p_x2,   g_x2);
        cudaGetSymbolAddress((void**)&p_ffh,  g_ffh);
        cudaGetSymbolAddress((void**)&p_ffo,  g_ffo);
        __nv_bfloat16* base;
        cudaGetSymbolAddress((void**)&base, b_xin); pb_xin[0]=base; pb_xin[1]=base+(size_t)NTOK*512;
        cudaGetSymbolAddress((void**)&base, b_ao ); pb_ao [0]=base; pb_ao [1]=base+(size_t)NTOK*512;
        cudaGetSymbolAddress((void**)&base, b_lg ); pb_lg [0]=base; pb_lg [1]=base+(size_t)NTOK*128;
        cudaGetSymbolAddress((void**)&base, b_x2 ); pb_x2 [0]=base; pb_x2 [1]=base+(size_t)NTOK*512;
        cudaGetSymbolAddress((void**)&base, b_ffh); pb_ffh[0]=base; pb_ffh[1]=base+(size_t)NTOK*2048;
        cudaGetSymbolAddress((void**)&base, b_w1 ); pb_w1 [0]=base; pb_w1 [1]=base+(size_t)1536*512;
        cudaGetSymbolAddress((void**)&base, b_w2 ); pb_w2 [0]=base; pb_w2 [1]=base+(size_t)512*512;
        cudaGetSymbolAddress((void**)&base, b_uw ); pb_uw [0]=base; pb_uw [1]=base+(size_t)512*128;
        cudaGetSymbolAddress((void**)&base, b_w3 ); pb_w3 [0]=base; pb_w3 [1]=base+(size_t)2048*512;
        cudaGetSymbolAddress((void**)&base, b_w4 ); pb_w4 [0]=base; pb_w4 [1]=base+(size_t)512*2048;
        cudaFuncSetAttribute(tgemm<0>, cudaFuncAttributeMaxDynamicSharedMemorySize, T_SMEM);
        cudaFuncSetAttribute(tgemm<1>, cudaFuncAttributeMaxDynamicSharedMemorySize, T_SMEM);
        cudaFuncSetAttribute(tgemm<2>, cudaFuncAttributeMaxDynamicSharedMemorySize, T_SMEM);
        init_done = true;
    }

    float* out_x = (float*)d_out;
    float* out_hidden = out_x + (size_t)NTOK * TE;
    float* out_stack  = out_hidden + (size_t)NTOK * TDH;

    // weight + input splits
    split_launch(in_proj_w, pb_w1[0], pb_w1[1], (size_t)1536*512);
    split_launch(out_proj_w, pb_w2[0], pb_w2[1], (size_t)512*512);
    split_launch(U_w, pb_uw[0], pb_uw[1], (size_t)512*128);
    split_launch(ffi_w, pb_w3[0], pb_w3[1], (size_t)2048*512);
    split_launch(ffo_w, pb_w4[0], pb_w4[1], (size_t)512*2048);
    split_launch(x_in, pb_xin[0], pb_xin[1], (size_t)NTOK*512);

    // 1) qkv
    tgemm<0><<<dim3(12,64),256,T_SMEM>>>(pb_xin[0], pb_xin[1], pb_w1[0], pb_w1[1],
                                         in_proj_b, nullptr, p_qkv, NTOK, 1536, 512);
    // 2) attention
    attn_kernel<<<dim3(16,64),256>>>(p_qkv, p_ao);
    // 3) out projection
    split_launch(p_ao, pb_ao[0], pb_ao[1], (size_t)NTOK*512);
    tgemm<0><<<dim3(4,64),256,T_SMEM>>>(pb_ao[0], pb_ao[1], pb_w2[0], pb_w2[1],
                                        out_proj_b, nullptr, p_proj, NTOK, 512, 512);
    // 4) x1 = nonsat(LN(x_in + proj))
    add_ln_kernel<true><<<NTOK,256>>>(x_in, p_proj, ln1_g, ln1_b, p_x1);
    // 5) hidden
    hidden_gemm<<<dim3(4,128),256>>>(p_x1, hidden_prev, stack_prev,
                                     W_w, R_w, P_w, W_b, R_b, P_b, out_hidden);
    // 6) logits
    logits_gemm<<<dim3(2,128),256>>>(p_x1, out_hidden, V_w, p_lg);
    // 7) softmax
    softmax128_kernel<<<NTOK/8,256>>>(p_lg);
    // 8) x2 = 0.5*(x1 + sm @ U_w.T)
    split_launch(p_lg, pb_lg[0], pb_lg[1], (size_t)NTOK*128);
    tgemm<2><<<dim3(4,64),256,T_SMEM>>>(pb_lg[0], pb_lg[1], pb_uw[0], pb_uw[1],
                                        nullptr, p_x1, p_x2, NTOK, 512, 128);
    // 9) stack
    stack_kernel<<<NTOK,128>>>(out_hidden, stack_prev, A_w, A_b, D_w, D_b, out_stack);
    // 10) ff hidden
    split_launch(p_x2, pb_x2[0], pb_x2[1], (size_t)NTOK*512);
    tgemm<1><<<dim3(16,64),256,T_SMEM>>>(pb_x2[0], pb_x2[1], pb_w3[0], pb_w3[1],
                                         ffi_b, nullptr, p_ffh, NTOK, 2048, 512);
    // 11) ff out
    split_launch(p_ffh, pb_ffh[0], pb_ffh[1], (size_t)NTOK*2048);
    tgemm<0><<<dim3(4,64),256,T_SMEM>>>(pb_ffh[0], pb_ffh[1], pb_w4[0], pb_w4[1],
                                        ffo_b, nullptr, p_ffo, NTOK, 512, 2048);
    // 12) x_out
    add_ln_kernel<false><<<NTOK,256>>>(p_x2, p_ffo, ln2_g, ln2_b, out_x);
}

// round 6
// speedup vs baseline: 3.0542x; 2.4686x over previous
#include <cuda_runtime.h>
#include <cuda_bf16.h>
#include <math.h>
#include <stdint.h>

#define TS 1024
#define TB 8
#define TE 512
#define TDH 256
#define TSW 96
#define NTOK 8192

// ---------------- fp32 scratch ----------------
__device__ __align__(16) float g_proj[(size_t)NTOK*TE];
__device__ __align__(16) float g_x1  [(size_t)NTOK*TE];
__device__ __align__(16) float g_lg  [(size_t)NTOK*128];
__device__ __align__(16) float g_x2  [(size_t)NTOK*TE];
__device__ __align__(16) float g_ffo [(size_t)NTOK*TE];

// ---------------- bf16 split scratch (hi/lo) ----------------
__device__ __align__(16) __nv_bfloat16 b_qkv[2][(size_t)NTOK*1536];
__device__ __align__(16) __nv_bfloat16 b_xin[2][(size_t)NTOK*512];
__device__ __align__(16) __nv_bfloat16 b_ao [2][(size_t)NTOK*512];
__device__ __align__(16) __nv_bfloat16 b_lg [2][(size_t)NTOK*128];
__device__ __align__(16) __nv_bfloat16 b_x2 [2][(size_t)NTOK*512];
__device__ __align__(16) __nv_bfloat16 b_ffh[2][(size_t)NTOK*2048];
__device__ __align__(16) __nv_bfloat16 b_w1 [2][1536*512];
__device__ __align__(16) __nv_bfloat16 b_w2 [2][512*512];
__device__ __align__(16) __nv_bfloat16 b_uw [2][512*128];
__device__ __align__(16) __nv_bfloat16 b_w3 [2][2048*512];
__device__ __align__(16) __nv_bfloat16 b_w4 [2][512*2048];

__device__ __forceinline__ float nonsat_f(float x) {
    float y = x;
#pragma unroll 1
    for (int it = 0; it < 32; ++it) {
        float y2 = y * y;
        float yn = __fdividef(0.66666668f * y * y2 + x, y2 + 1.0f);
        float d = fabsf(yn - y);
        y = yn;
        if (d <= 1e-6f) break;
    }
    return y;
}

__device__ __forceinline__ uint32_t su32(const void* p) {
    uint32_t a;
    asm("{ .reg .u64 t; cvta.to.shared.u64 t, %1; cvt.u32.u64 %0, t; }" : "=r"(a) : "l"(p));
    return a;
}
__device__ __forceinline__ void ldmx4(uint32_t* r, uint32_t addr) {
    asm volatile("ldmatrix.sync.aligned.m8n8.x4.shared.b16 {%0,%1,%2,%3}, [%4];"
        : "=r"(r[0]), "=r"(r[1]), "=r"(r[2]), "=r"(r[3]) : "r"(addr));
}
__device__ __forceinline__ void ldmx4t(uint32_t* r, uint32_t addr) {
    asm volatile("ldmatrix.sync.aligned.m8n8.x4.trans.shared.b16 {%0,%1,%2,%3}, [%4];"
        : "=r"(r[0]), "=r"(r[1]), "=r"(r[2]), "=r"(r[3]) : "r"(addr));
}
__device__ __forceinline__ void mma16816(float* c, const uint32_t* a, const uint32_t* b) {
    asm volatile(
        "mma.sync.aligned.m16n8k16.row.col.f32.bf16.bf16.f32 "
        "{%0,%1,%2,%3}, {%4,%5,%6,%7}, {%8,%9}, {%0,%1,%2,%3};\n"
        : "+f"(c[0]), "+f"(c[1]), "+f"(c[2]), "+f"(c[3])
        : "r"(a[0]), "r"(a[1]), "r"(a[2]), "r"(a[3]), "r"(b[0]), "r"(b[1]));
}
__device__ __forceinline__ uint32_t pkbf2(float lo, float hi) {
    uint32_t r;
    asm("cvt.rn.bf16x2.f32 %0, %1, %2;" : "=r"(r) : "f"(hi), "f"(lo));
    return r;
}
__device__ __forceinline__ void store_split2(__nv_bfloat16* H, __nv_bfloat16* L,
                                             size_t idx, float a, float b) {
    __nv_bfloat16 ha = __float2bfloat16(a);
    __nv_bfloat16 hb = __float2bfloat16(b);
    __nv_bfloat16 la = __float2bfloat16(a - __bfloat162float(ha));
    __nv_bfloat16 lb = __float2bfloat16(b - __bfloat162float(hb));
    union { __nv_bfloat16 x[2]; uint32_t u; } ph, pl;
    ph.x[0] = ha; ph.x[1] = hb; pl.x[0] = la; pl.x[1] = lb;
    *(uint32_t*)(H + idx) = ph.u;
    *(uint32_t*)(L + idx) = pl.u;
}

// ---------------- fp32 -> (bf16 hi, bf16 lo) split ----------------
__global__ void __launch_bounds__(256) split_kernel(
    const float* __restrict__ src, __nv_bfloat16* __restrict__ hi,
    __nv_bfloat16* __restrict__ lo, int n4)
{
    int i = blockIdx.x * 256 + threadIdx.x;
    if (i >= n4) return;
    float4 v = ((const float4*)src)[i];
    union { __nv_bfloat16 b[4]; uint2 u; } H, L;
    H.b[0] = __float2bfloat16(v.x); L.b[0] = __float2bfloat16(v.x - __bfloat162float(H.b[0]));
    H.b[1] = __float2bfloat16(v.y); L.b[1] = __float2bfloat16(v.y - __bfloat162float(H.b[1]));
    H.b[2] = __float2bfloat16(v.z); L.b[2] = __float2bfloat16(v.z - __bfloat162float(H.b[2]));
    H.b[3] = __float2bfloat16(v.w); L.b[3] = __float2bfloat16(v.w - __bfloat162float(H.b[3]));
    ((uint2*)hi)[i] = H.u;
    ((uint2*)lo)[i] = L.u;
}

// ---------------- HMMA split GEMM (ldmatrix) ----------------
// C(MxN) = A(MxK) @ W(NxK)^T via Ah*Wh + Ah*Wl + Al*Wh, fp32 accum
// EPI 0:+bias 1:nonsat(+bias) 2:0.5*(acc+res) ; OUT 0:fp32 C  1: split bf16 Ch/Cl
#define T_AH 0
#define T_AL 16384
#define T_BH 32768
#define T_BL 49152
#define T_SMEM 65536

template<int EPI, int OUT>
__global__ void __launch_bounds__(256) tgemm(
    const __nv_bfloat16* __restrict__ Ah, const __nv_bfloat16* __restrict__ Al,
    const __nv_bfloat16* __restrict__ Wh, const __nv_bfloat16* __restrict__ Wl,
    const float* __restrict__ bias, const float* __restrict__ res,
    float* __restrict__ C, __nv_bfloat16* __restrict__ Ch, __nv_bfloat16* __restrict__ Cl,
    int M, int N, int K)
{
    extern __shared__ char smem[];
    const uint32_t sbase = su32(smem);
    const int tid = threadIdx.x, wid = tid >> 5, lane = tid & 31;
    const int m0 = blockIdx.y * 128, n0 = blockIdx.x * 128;
    const int g = lane >> 2, t2 = (lane & 3) << 1;
    const int wr = (wid & 1) << 6;
    const int wc = (wid >> 1) << 5;
    const int l7 = lane & 7, lr15 = lane & 15;
    const uint32_t swz = (uint32_t)(l7 << 4);
    const int aklo = (lane >> 4) << 3;
    const int bklo = ((lane >> 3) & 1) << 3;
    const uint32_t arow = (uint32_t)((wr + lr15) << 7);
    const uint32_t brow = (uint32_t)((wc + l7 + ((lane >> 4) << 3)) << 7);

    float c[4][4][4];
#pragma unroll
    for (int i = 0; i < 4; i++)
#pragma unroll
        for (int j = 0; j < 4; j++)
#pragma unroll
            for (int q = 0; q < 4; q++) c[i][j][q] = 0.f;

    const int nch = K >> 6;
    for (int ch = 0; ch < nch; ch++) {
        const int k0 = ch << 6;
#pragma unroll
        for (int t = 0; t < 4; t++) {
            int e = tid + (t << 8);
            int r = e >> 3, q = e & 7;
            uint32_t off = (uint32_t)((r << 7) + (q << 4));
            off ^= (off >> 3) & 0x70;
            const size_t ga = (size_t)(m0 + r) * K + k0 + (q << 3);
            const size_t gb = (size_t)(n0 + r) * K + k0 + (q << 3);
            *(uint4*)(smem + T_AH + off) = *(const uint4*)(Ah + ga);
            *(uint4*)(smem + T_AL + off) = *(const uint4*)(Al + ga);
            *(uint4*)(smem + T_BH + off) = *(const uint4*)(Wh + gb);
            *(uint4*)(smem + T_BL + off) = *(const uint4*)(Wl + gb);
        }
        __syncthreads();
#pragma unroll
        for (int kk = 0; kk < 64; kk += 16) {
            uint32_t bh[2][4], bl[2][4];
            const uint32_t boff = ((uint32_t)((kk + bklo) << 1)) ^ swz;
#pragma unroll
            for (int bi = 0; bi < 2; bi++) {
                ldmx4(bh[bi], sbase + T_BH + brow + (uint32_t)(bi << 11) + boff);
                ldmx4(bl[bi], sbase + T_BL + brow + (uint32_t)(bi << 11) + boff);
            }
            const uint32_t aoff = ((uint32_t)((kk + aklo) << 1)) ^ swz;
#pragma unroll
            for (int mi = 0; mi < 4; mi++) {
                uint32_t ah[4], al[4];
                ldmx4(ah, sbase + T_AH + arow + (uint32_t)(mi << 11) + aoff);
                ldmx4(al, sbase + T_AL + arow + (uint32_t)(mi << 11) + aoff);
#pragma unroll
                for (int bi = 0; bi < 2; bi++) {
                    mma16816(c[mi][2*bi],   ah, &bh[bi][0]);
                    mma16816(c[mi][2*bi],   ah, &bl[bi][0]);
                    mma16816(c[mi][2*bi],   al, &bh[bi][0]);
                    mma16816(c[mi][2*bi+1], ah, &bh[bi][2]);
                    mma16816(c[mi][2*bi+1], ah, &bl[bi][2]);
                    mma16816(c[mi][2*bi+1], al, &bh[bi][2]);
                }
            }
        }
        __syncthreads();
    }

#pragma unroll
    for (int mi = 0; mi < 4; mi++) {
#pragma unroll
        for (int ni = 0; ni < 4; ni++) {
            int row = m0 + wr + (mi << 4) + g;
            int col = n0 + wc + (ni << 3) + t2;
#pragma unroll
            for (int h = 0; h < 2; h++) {
                int rr = row + h * 8;
                float v0 = c[mi][ni][2 * h], v1 = c[mi][ni][2 * h + 1];
                if (EPI == 0) {
                    v0 += bias[col]; v1 += bias[col + 1];
                } else if (EPI == 1) {
                    v0 = nonsat_f(v0 + bias[col]); v1 = nonsat_f(v1 + bias[col + 1]);
                } else {
                    const float2 rv = *(const float2*)(res + (size_t)rr * N + col);
                    v0 = 0.5f * (v0 + rv.x); v1 = 0.5f * (v1 + rv.y);
                }
                if (OUT == 0) {
                    float2 o; o.x = v0; o.y = v1;
                    *(float2*)(C + (size_t)rr * N + col) = o;
                } else {
                    store_split2(Ch, Cl, (size_t)rr * N + col, v0, v1);
                }
            }
        }
    }
}

// ---------------- HMMA flash attention (causal), split-bf16 ----------------
// Q/K: 3-term split for S; P: bf16; V: 2-term split for PV. Writes split ao.
__global__ void __launch_bounds__(128) attn_kernel(
    const __nv_bfloat16* __restrict__ QH, const __nv_bfloat16* __restrict__ QL,
    __nv_bfloat16* __restrict__ aoh, __nv_bfloat16* __restrict__ aol)
{
    __shared__ __align__(16) char sm[49152];
    // QH 0, QL 8192, KH 16384, KL 24576, VH 32768, VL 40960
    const int qt = blockIdx.x, q0 = qt << 6;
    const int b = blockIdx.y >> 3, h = blockIdx.y & 7;
    const int tid = threadIdx.x, wid = tid >> 5, lane = tid & 31;
    const int g = lane >> 2, t2 = (lane & 3) << 1;
    const uint32_t sbase = su32(sm);
    const int l7 = lane & 7, lr15 = lane & 15;
    const uint32_t swz = (uint32_t)(l7 << 4);
    const int klo8 = (lane >> 4) << 3;
    const int bk8 = ((lane >> 3) & 1) << 3;
    const int wq = wid << 4;

    // load Q tile once
    const size_t qbase = ((size_t)q0 * TB + b) * 1536 + h * 64;
#pragma unroll
    for (int t = 0; t < 4; t++) {
        int e = tid + (t << 7);
        int r = e >> 3, q = e & 7;
        uint32_t off = (uint32_t)((r << 7) + (q << 4));
        off ^= (off >> 3) & 0x70;
        const size_t gs = qbase + (size_t)r * (TB * 1536) + (q << 3);
        *(uint4*)(sm + 0    + off) = *(const uint4*)(QH + gs);
        *(uint4*)(sm + 8192 + off) = *(const uint4*)(QL + gs);
    }

    float o[8][4];
#pragma unroll
    for (int i = 0; i < 8; i++)
#pragma unroll
        for (int j = 0; j < 4; j++) o[i][j] = 0.f;
    float m0 = -1e30f, m1 = -1e30f, l0 = 0.f, l1 = 0.f;

    const uint32_t aA = sbase + (uint32_t)((wq + lr15) << 7);
    const uint32_t browB = sbase + (uint32_t)((l7 + ((lane >> 4) << 3)) << 7);
    const uint32_t vrow  = sbase + (uint32_t)((l7 + (((lane >> 3) & 1) << 3)) << 7);

    for (int kt = 0; kt <= qt; kt++) {
        const int kv0 = kt << 6;
        __syncthreads();
        const size_t kbase = ((size_t)kv0 * TB + b) * 1536 + h * 64;
#pragma unroll
        for (int t = 0; t < 4; t++) {
            int e = tid + (t << 7);
            int r = e >> 3, q = e & 7;
            uint32_t off = (uint32_t)((r << 7) + (q << 4));
            off ^= (off >> 3) & 0x70;
            const size_t gk = kbase + (size_t)r * (TB * 1536) + 512 + (q << 3);
            const size_t gv = kbase + (size_t)r * (TB * 1536) + 1024 + (q << 3);
            *(uint4*)(sm + 16384 + off) = *(const uint4*)(QH + gk);
            *(uint4*)(sm + 24576 + off) = *(const uint4*)(QL + gk);
            *(uint4*)(sm + 32768 + off) = *(const uint4*)(QH + gv);
            *(uint4*)(sm + 40960 + off) = *(const uint4*)(QL + gv);
        }
        __syncthreads();

        float sc[8][4];
#pragma unroll
        for (int i = 0; i < 8; i++)
#pragma unroll
            for (int j = 0; j < 4; j++) sc[i][j] = 0.f;
#pragma unroll
        for (int kk = 0; kk < 64; kk += 16) {
            uint32_t qh[4], ql[4];
            const uint32_t aoff = ((uint32_t)((kk + klo8) << 1)) ^ swz;
            ldmx4(qh, aA + 0    + aoff);
            ldmx4(ql, aA + 8192 + aoff);
            const uint32_t boff = ((uint32_t)((kk + bk8) << 1)) ^ swz;
#pragma unroll
            for (int bi = 0; bi < 4; bi++) {
                uint32_t kh[4], kl[4];
                ldmx4(kh, browB + 16384 + (uint32_t)(bi << 11) + boff);
                ldmx4(kl, browB + 24576 + (uint32_t)(bi << 11) + boff);
                mma16816(sc[2*bi],   qh, &kh[0]);
                mma16816(sc[2*bi],   qh, &kl[0]);
                mma16816(sc[2*bi],   ql, &kh[0]);
                mma16816(sc[2*bi+1], qh, &kh[2]);
                mma16816(sc[2*bi+1], qh, &kl[2]);
                mma16816(sc[2*bi+1], ql, &kh[2]);
            }
        }

        // scale + causal mask + online softmax
        const int r0 = q0 + wq + g, r1 = r0 + 8;
        const bool diag = (kt == qt);
        float tm0 = -1e30f, tm1 = -1e30f;
#pragma unroll
        for (int ni = 0; ni < 8; ni++) {
            const int cb = kv0 + (ni << 3) + t2;
            float s0 = sc[ni][0] * 0.125f, s1 = sc[ni][1] * 0.125f;
            float s2 = sc[ni][2] * 0.125f, s3 = sc[ni][3] * 0.125f;
            if (diag) {
                if (cb     > r0) s0 = -1e30f;
                if (cb + 1 > r0) s1 = -1e30f;
                if (cb     > r1) s2 = -1e30f;
                if (cb + 1 > r1) s3 = -1e30f;
            }
            sc[ni][0] = s0; sc[ni][1] = s1; sc[ni][2] = s2; sc[ni][3] = s3;
            tm0 = fmaxf(tm0, fmaxf(s0, s1));
            tm1 = fmaxf(tm1, fmaxf(s2, s3));
        }
        tm0 = fmaxf(tm0, __shfl_xor_sync(0xffffffffu, tm0, 1));
        tm0 = fmaxf(tm0, __shfl_xor_sync(0xffffffffu, tm0, 2));
        tm1 = fmaxf(tm1, __shfl_xor_sync(0xffffffffu, tm1, 1));
        tm1 = fmaxf(tm1, __shfl_xor_sync(0xffffffffu, tm1, 2));
        const float mn0 = fmaxf(m0, tm0), mn1 = fmaxf(m1, tm1);
        const float al0 = __expf(m0 - mn0), al1 = __expf(m1 - mn1);
        m0 = mn0; m1 = mn1;
        float ps0 = 0.f, ps1 = 0.f;
#pragma unroll
        for (int ni = 0; ni < 8; ni++) {
            float p0 = __expf(sc[ni][0] - m0), p1 = __expf(sc[ni][1] - m0);
            float p2 = __expf(sc[ni][2] - m1), p3 = __expf(sc[ni][3] - m1);
            sc[ni][0] = p0; sc[ni][1] = p1; sc[ni][2] = p2; sc[ni][3] = p3;
            ps0 += p0 + p1; ps1 += p2 + p3;
        }
        ps0 += __shfl_xor_sync(0xffffffffu, ps0, 1);
        ps0 += __shfl_xor_sync(0xffffffffu, ps0, 2);
        ps1 += __shfl_xor_sync(0xffffffffu, ps1, 1);
        ps1 += __shfl_xor_sync(0xffffffffu, ps1, 2);
        l0 = l0 * al0 + ps0;
        l1 = l1 * al1 + ps1;
#pragma unroll
        for (int ni = 0; ni < 8; ni++) {
            o[ni][0] *= al0; o[ni][1] *= al0;
            o[ni][2] *= al1; o[ni][3] *= al1;
        }

        // PV
#pragma unroll
        for (int j = 0; j < 4; j++) {
            uint32_t pa[4];
            pa[0] = pkbf2(sc[2*j][0],   sc[2*j][1]);
            pa[1] = pkbf2(sc[2*j][2],   sc[2*j][3]);
            pa[2] = pkbf2(sc[2*j+1][0], sc[2*j+1][1]);
            pa[3] = pkbf2(sc[2*j+1][2], sc[2*j+1][3]);
#pragma unroll
            for (int i = 0; i < 4; i++) {
                uint32_t vh[4], vl[4];
                const uint32_t voff = (uint32_t)(j << 11) +
                    (((uint32_t)(((i << 4) + klo8) << 1)) ^ swz);
                ldmx4t(vh, vrow + 32768 + voff);
                ldmx4t(vl, vrow + 40960 + voff);
                mma16816(o[2*i],   pa, &vh[0]);
                mma16816(o[2*i],   pa, &vl[0]);
                mma16816(o[2*i+1], pa, &vh[2]);
                mma16816(o[2*i+1], pa, &vl[2]);
            }
        }
    }

    const float inv0 = __fdividef(1.f, l0), inv1 = __fdividef(1.f, l1);
    const int qg0 = q0 + wq + g;
    const size_t dst0 = ((size_t)qg0 * TB + b) * 512 + h * 64 + t2;
    const size_t dst1 = dst0 + (size_t)8 * TB * 512;
#pragma unroll
    for (int ni = 0; ni < 8; ni++) {
        const int d = ni << 3;
        store_split2(aoh, aol, dst0 + d, o[ni][0] * inv0, o[ni][1] * inv0);
        store_split2(aoh, aol, dst1 + d, o[ni][2] * inv1, o[ni][3] * inv1);
    }
}

template<bool NS>
__global__ void __launch_bounds__(256) add_ln_kernel(
    const float* __restrict__ xa, const float* __restrict__ xb,
    const float* __restrict__ g, const float* __restrict__ bl,
    float* __restrict__ out)
{
    const int t = blockIdx.x, tid = threadIdx.x;
    __shared__ float red[8];
    const size_t base = (size_t)t * TE;
    float v0 = xa[base+tid] + xb[base+tid];
    float v1 = xa[base+tid+256] + xb[base+tid+256];
    float s = v0 + v1;
#pragma unroll
    for (int o = 16; o; o >>= 1) s += __shfl_xor_sync(0xffffffffu, s, o);
    if ((tid & 31) == 0) red[tid>>5] = s;
    __syncthreads();
    if (tid == 0) { float tt=0; for (int w=0;w<8;w++) tt+=red[w]; red[0]=tt; }
    __syncthreads();
    const float mean = red[0] * (1.0f/512.0f);
    __syncthreads();
    float d0 = v0-mean, d1 = v1-mean;
    float q = d0*d0 + d1*d1;
#pragma unroll
    for (int o = 16; o; o >>= 1) q += __shfl_xor_sync(0xffffffffu, q, o);
    if ((tid & 31) == 0) red[tid>>5] = q;
    __syncthreads();
    if (tid == 0) { float tt=0; for (int w=0;w<8;w++) tt+=red[w]; red[0]=tt; }
    __syncthreads();
    const float rs = rsqrtf(red[0]*(1.0f/512.0f) + 1e-5f);
    float o0 = d0*rs*g[tid]     + bl[tid];
    float o1 = d1*rs*g[tid+256] + bl[tid+256];
    if (NS) { o0 = nonsat_f(o0); o1 = nonsat_f(o1); }
    out[base+tid] = o0;
    out[base+tid+256] = o1;
}

__global__ void __launch_bounds__(256) hidden_gemm(
    const float* __restrict__ x1, const float* __restrict__ hp,
    const float* __restrict__ sp,
    const float* __restrict__ Ww, const float* __restrict__ Rw, const float* __restrict__ Pw,
    const float* __restrict__ Wb, const float* __restrict__ Rb, const float* __restrict__ Pb,
    float* __restrict__ out)
{
    __shared__ __align__(16) float As[16][68];
    __shared__ __align__(16) float Bs[16][68];
    const int m0 = blockIdx.y * 64, n0 = blockIdx.x * 64;
    const int tid = threadIdx.x;
    const int lr = tid >> 2, lc = (tid & 3) << 2;
    const int tx = tid & 15, ty = tid >> 4;
    const int u = m0 + lr;
    const int tp = ((u & (TS-1)) << 3) | (u >> 10);
    const float* A0 = x1 + (size_t)tp * TE;
    const float* A1 = hp + (size_t)u * TDH - 512;
    const float* A2 = sp + (size_t)u * 4608 - 768;
    const int nr = n0 + lr;
    const float* W0 = Ww + (size_t)nr * TE;
    const float* W1 = Rw + (size_t)nr * TDH - 512;
    const float* W2 = Pw + (size_t)nr * TSW - 768;
    float acc[4][4];
#pragma unroll
    for (int i=0;i<4;i++)
#pragma unroll
        for (int j=0;j<4;j++) acc[i][j]=0.f;
    for (int k0 = 0; k0 < 864; k0 += 16) {
        const int k = k0 + lc;
        const float* ap = (k < 512) ? (A0 + k) : ((k < 768) ? (A1 + k) : (A2 + k));
        const float* wp = (k < 512) ? (W0 + k) : ((k < 768) ? (W1 + k) : (W2 + k));
        float4 av = *(const float4*)ap;
        float4 wv = *(const float4*)wp;
        As[lc+0][lr]=av.x; As[lc+1][lr]=av.y; As[lc+2][lr]=av.z; As[lc+3][lr]=av.w;
        Bs[lc+0][lr]=wv.x; Bs[lc+1][lr]=wv.y; Bs[lc+2][lr]=wv.z; Bs[lc+3][lr]=wv.w;
        __syncthreads();
#pragma unroll
        for (int kk = 0; kk < 16; kk++) {
            float4 a = *(const float4*)&As[kk][ty<<2];
            float4 b = *(const float4*)&Bs[kk][tx<<2];
            float aa[4]={a.x,a.y,a.z,a.w}, bb[4]={b.x,b.y,b.z,b.w};
#pragma unroll
            for (int i=0;i<4;i++)
#pragma unroll
                for (int j=0;j<4;j++) acc[i][j]+=aa[i]*bb[j];
        }
        __syncthreads();
    }
#pragma unroll
    for (int i = 0; i < 4; i++) {
        int uu = m0 + (ty<<2) + i;
        float4 o; float* op=&o.x;
#pragma unroll
        for (int j = 0; j < 4; j++) {
            int nn = n0 + (tx<<2) + j;
            op[j] = nonsat_f(acc[i][j] + Wb[nn] + Rb[nn] + Pb[nn]);
        }
        *(float4*)(out + (size_t)uu*TDH + n0 + (tx<<2)) = o;
    }
}

__global__ void __launch_bounds__(256) logits_gemm(
    const float* __restrict__ x1, const float* __restrict__ hid,
    const float* __restrict__ Vw, float* __restrict__ out)
{
    __shared__ __align__(16) float As[16][68];
    __shared__ __align__(16) float Bs[16][68];
    const int m0 = blockIdx.y * 64, n0 = blockIdx.x * 64;
    const int tid = threadIdx.x;
    const int lr = tid >> 2, lc = (tid & 3) << 2;
    const int tx = tid & 15, ty = tid >> 4;
    const int t = m0 + lr;
    const int up = ((t & 7) << 10) | (t >> 3);
    const float* A0 = x1 + (size_t)t * TE;
    const float* A1 = hid + (size_t)up * TDH - 512;
    const float* Wp = Vw + (size_t)(n0 + lr) * 768 + lc;
    float acc[4][4];
#pragma unroll
    for (int i=0;i<4;i++)
#pragma unroll
        for (int j=0;j<4;j++) acc[i][j]=0.f;
    for (int k0 = 0; k0 < 768; k0 += 16) {
        const int k = k0 + lc;
        const float* ap = (k < 512) ? (A0 + k) : (A1 + k);
        float4 av = *(const float4*)ap;
        float4 wv = *(const float4*)(Wp + k0);
        As[lc+0][lr]=av.x; As[lc+1][lr]=av.y; As[lc+2][lr]=av.z; As[lc+3][lr]=av.w;
        Bs[lc+0][lr]=wv.x; Bs[lc+1][lr]=wv.y; Bs[lc+2][lr]=wv.z; Bs[lc+3][lr]=wv.w;
        __syncthreads();
#pragma unroll
        for (int kk = 0; kk < 16; kk++) {
            float4 a = *(const float4*)&As[kk][ty<<2];
            float4 b = *(const float4*)&Bs[kk][tx<<2];
            float aa[4]={a.x,a.y,a.z,a.w}, bb[4]={b.x,b.y,b.z,b.w};
#pragma unroll
            for (int i=0;i<4;i++)
#pragma unroll
                for (int j=0;j<4;j++) acc[i][j]+=aa[i]*bb[j];
        }
        __syncthreads();
    }
#pragma unroll
    for (int i = 0; i < 4; i++) {
        int m = m0 + (ty<<2) + i;
        float4 o; o.x=acc[i][0]; o.y=acc[i][1]; o.z=acc[i][2]; o.w=acc[i][3];
        *(float4*)(out + (size_t)m*128 + n0 + (tx<<2)) = o;
    }
}

__global__ void __launch_bounds__(256) softmax128_kernel(float* __restrict__ lg)
{
    const int t = blockIdx.x * 8 + (threadIdx.x >> 5);
    const int lane = threadIdx.x & 31;
    float4* p = (float4*)(lg + (size_t)t * 128) + lane;
    float4 v = *p;
    float mx = fmaxf(fmaxf(v.x, v.y), fmaxf(v.z, v.w));
#pragma unroll
    for (int o = 16; o; o >>= 1) mx = fmaxf(mx, __shfl_xor_sync(0xffffffffu, mx, o));
    v.x = __expf(v.x-mx); v.y = __expf(v.y-mx); v.z = __expf(v.z-mx); v.w = __expf(v.w-mx);
    float s = v.x + v.y + v.z + v.w;
#pragma unroll
    for (int o = 16; o; o >>= 1) s += __shfl_xor_sync(0xffffffffu, s, o);
    float is = __fdividef(1.f, s);
    v.x *= is; v.y *= is; v.z *= is; v.w *= is;
    *p = v;
}

__global__ void __launch_bounds__(128) stack_kernel(
    const float* __restrict__ hidden, const float* __restrict__ sp,
    const float* __restrict__ Aw, const float* __restrict__ Ab,
    const float* __restrict__ Dw, const float* __restrict__ Db,
    float* __restrict__ out)
{
    __shared__ __align__(16) float h[256];
    __shared__ __align__(16) float inp[96];
    __shared__ float ctl[3];
    const int u = blockIdx.x, tid = threadIdx.x;
    const float* hrow = hidden + (size_t)u * 256;
    h[tid] = hrow[tid]; h[tid+128] = hrow[tid+128];
    __syncthreads();
    if (tid < 96) {
        const float* w = Dw + tid * 256;
        float s = Db[tid];
        for (int k = 0; k < 256; k += 4) {
            float4 wv = *(const float4*)(w + k);
            s += wv.x*h[k] + wv.y*h[k+1] + wv.z*h[k+2] + wv.w*h[k+3];
        }
        inp[tid] = nonsat_f(s);
    } else if (tid < 99) {
        int i = tid - 96;
        const float* w = Aw + i * 256;
        float s = Ab[i];
        for (int k = 0; k < 256; k++) s += w[k]*h[k];
        ctl[i] = s;
    }
    __syncthreads();
    float mx = fmaxf(ctl[0], fmaxf(ctl[1], ctl[2]));
    float e0 = __expf(ctl[0]-mx), e1 = __expf(ctl[1]-mx), e2 = __expf(ctl[2]-mx);
    float is = __fdividef(1.f, e0+e1+e2);
    float c0 = e0*is, c1 = e1*is, c2 = e2*is;
    const float4* prev = (const float4*)(sp + (size_t)u * 4608);
    float4* dst = (float4*)(out + (size_t)u * 4608);
    const float4* inp4 = (const float4*)inp;
    for (int idx = tid; idx < 1152; idx += 128) {
        int d = idx / 24;
        float4 p = prev[idx];
        float4 up = (d == 0) ? inp4[idx] : prev[idx-24];
        float4 dn;
        if (d == 47) { dn.x=dn.y=dn.z=dn.w=0.f; } else dn = prev[idx+24];
        float4 o;
        o.x = c2*p.x + c0*up.x + c1*dn.x;
        o.y = c2*p.y + c0*up.y + c1*dn.y;
        o.z = c2*p.z + c0*up.z + c1*dn.z;
        o.w = c2*p.w + c0*up.w + c1*dn.w;
        dst[idx] = o;
    }
}

static inline void split_launch(const float* src, __nv_bfloat16* hi, __nv_bfloat16* lo, size_t n) {
    int n4 = (int)(n >> 2);
    split_kernel<<<(n4 + 255) / 256, 256>>>(src, hi, lo, n4);
}

extern "C" void kernel_launch(void* const* d_in, const int* in_sizes, int n_in,
                              void* d_out, int out_size) {
    const float* x_in = (const float*)d_in[0];
    const float* hidden_prev = (const float*)d_in[1];
    const float* stack_prev  = (const float*)d_in[2];
    const float* in_proj_w = (const float*)d_in[3];
    const float* in_proj_b = (const float*)d_in[4];
    const float* out_proj_w = (const float*)d_in[5];
    const float* out_proj_b = (const float*)d_in[6];
    const float* ln1_g = (const float*)d_in[7];
    const float* ln1_b = (const float*)d_in[8];
    const float* ln2_g = (const float*)d_in[9];
    const float* ln2_b = (const float*)d_in[10];
    const float* W_w = (const float*)d_in[11];
    const float* W_b = (const float*)d_in[12];
    const float* R_w = (const float*)d_in[13];
    const float* R_b = (const float*)d_in[14];
    const float* P_w = (const float*)d_in[15];
    const float* P_b = (const float*)d_in[16];
    const float* V_w = (const float*)d_in[17];
    const float* U_w = (const float*)d_in[18];
    const float* A_w = (const float*)d_in[19];
    const float* A_b = (const float*)d_in[20];
    const float* D_w = (const float*)d_in[21];
    const float* D_b = (const float*)d_in[22];
    const float* ffi_w = (const float*)d_in[23];
    const float* ffi_b = (const float*)d_in[24];
    const float* ffo_w = (const float*)d_in[25];
    const float* ffo_b = (const float*)d_in[26];

    static bool init_done = false;
    static float *p_proj,*p_x1,*p_lg,*p_x2,*p_ffo;
    static __nv_bfloat16 *pb_qkv[2],*pb_xin[2],*pb_ao[2],*pb_lg[2],*pb_x2[2],*pb_ffh[2];
    static __nv_bfloat16 *pb_w1[2],*pb_w2[2],*pb_uw[2],*pb_w3[2],*pb_w4[2];
    if (!init_done) {
        cudaGetSymbolAddress((void**)&p_proj, g_proj);
        cudaGetSymbolAddress((void**)&p_x1,   g_x1);
        cudaGetSymbolAddress((void**)&p_lg,   g_lg);
        cudaGetSymbolAddress((void**)&p_x2,   g_x2);
        cudaGetSymbolAddress((void**)&p_ffo,  g_ffo);
        __nv_bfloat16* base;
        cudaGetSymbolAddress((void**)&base, b_qkv); pb_qkv[0]=base; pb_qkv[1]=base+(size_t)NTOK*1536;
        cudaGetSymbolAddress((void**)&base, b_xin); pb_xin[0]=base; pb_xin[1]=base+(size_t)NTOK*512;
        cudaGetSymbolAddress((void**)&base, b_ao ); pb_ao [0]=base; pb_ao [1]=base+(size_t)NTOK*512;
        cudaGetSymbolAddress((void**)&base, b_lg ); pb_lg [0]=base; pb_lg [1]=base+(size_t)NTOK*128;
        cudaGetSymbolAddress((void**)&base, b_x2 ); pb_x2 [0]=base; pb_x2 [1]=base+(size_t)NTOK*512;
        cudaGetSymbolAddress((void**)&base, b_ffh); pb_ffh[0]=base; pb_ffh[1]=base+(size_t)NTOK*2048;
        cudaGetSymbolAddress((void**)&base, b_w1 ); pb_w1 [0]=base; pb_w1 [1]=base+(size_t)1536*512;
        cudaGetSymbolAddress((void**)&base, b_w2 ); pb_w2 [0]=base; pb_w2 [1]=base+(size_t)512*512;
        cudaGetSymbolAddress((void**)&base, b_uw ); pb_uw [0]=base; pb_uw [1]=base+(size_t)512*128;
        cudaGetSymbolAddress((void**)&base, b_w3 ); pb_w3 [0]=base; pb_w3 [1]=base+(size_t)2048*512;
        cudaGetSymbolAddress((void**)&base, b_w4 ); pb_w4 [0]=base; pb_w4 [1]=base+(size_t)512*2048;
        cudaFuncSetAttribute(tgemm<0,0>, cudaFuncAttributeMaxDynamicSharedMemorySize, T_SMEM);
        cudaFuncSetAttribute(tgemm<0,1>, cudaFuncAttributeMaxDynamicSharedMemorySize, T_SMEM);
        cudaFuncSetAttribute(tgemm<1,1>, cudaFuncAttributeMaxDynamicSharedMemorySize, T_SMEM);
        cudaFuncSetAttribute(tgemm<2,0>, cudaFuncAttributeMaxDynamicSharedMemorySize, T_SMEM);
        init_done = true;
    }

    float* out_x = (float*)d_out;
    float* out_hidden = out_x + (size_t)NTOK * TE;
    float* out_stack  = out_hidden + (size_t)NTOK * TDH;

    // splits: weights + x_in
    split_launch(in_proj_w, pb_w1[0], pb_w1[1], (size_t)1536*512);
    split_launch(out_proj_w, pb_w2[0], pb_w2[1], (size_t)512*512);
    split_launch(U_w, pb_uw[0], pb_uw[1], (size_t)512*128);
    split_launch(ffi_w, pb_w3[0], pb_w3[1], (size_t)2048*512);
    split_launch(ffo_w, pb_w4[0], pb_w4[1], (size_t)512*2048);
    split_launch(x_in, pb_xin[0], pb_xin[1], (size_t)NTOK*512);

    // 1) qkv (writes split bf16 directly)
    tgemm<0,1><<<dim3(12,64),256,T_SMEM>>>(pb_xin[0], pb_xin[1], pb_w1[0], pb_w1[1],
        in_proj_b, nullptr, nullptr, pb_qkv[0], pb_qkv[1], NTOK, 1536, 512);
    // 2) HMMA flash attention (reads/writes split)
    attn_kernel<<<dim3(16,64),128>>>(pb_qkv[0], pb_qkv[1], pb_ao[0], pb_ao[1]);
    // 3) out projection
    tgemm<0,0><<<dim3(4,64),256,T_SMEM>>>(pb_ao[0], pb_ao[1], pb_w2[0], pb_w2[1],
        out_proj_b, nullptr, p_proj, nullptr, nullptr, NTOK, 512, 512);
    // 4) x1 = nonsat(LN(x_in + proj))
    add_ln_kernel<true><<<NTOK,256>>>(x_in, p_proj, ln1_g, ln1_b, p_x1);
    // 5) hidden
    hidden_gemm<<<dim3(4,128),256>>>(p_x1, hidden_prev, stack_prev,
                                     W_w, R_w, P_w, W_b, R_b, P_b, out_hidden);
    // 6) logits
    logits_gemm<<<dim3(2,128),256>>>(p_x1, out_hidden, V_w, p_lg);
    // 7) softmax
    softmax128_kernel<<<NTOK/8,256>>>(p_lg);
    // 8) x2 = 0.5*(x1 + sm @ U_w.T)
    split_launch(p_lg, pb_lg[0], pb_lg[1], (size_t)NTOK*128);
    tgemm<2,0><<<dim3(4,64),256,T_SMEM>>>(pb_lg[0], pb_lg[1], pb_uw[0], pb_uw[1],
        nullptr, p_x1, p_x2, nullptr, nullptr, NTOK, 512, 128);
    // 9) stack
    stack_kernel<<<NTOK,128>>>(out_hidden, stack_prev, A_w, A_b, D_w, D_b, out_stack);
    // 10) ff hidden (writes split directly)
    split_launch(p_x2, pb_x2[0], pb_x2[1], (size_t)NTOK*512);
    tgemm<1,1><<<dim3(16,64),256,T_SMEM>>>(pb_x2[0], pb_x2[1], pb_w3[0], pb_w3[1],
        ffi_b, nullptr, nullptr, pb_ffh[0], pb_ffh[1], NTOK, 2048, 512);
    // 11) ff out
    tgemm<0,0><<<dim3(4,64),256,T_SMEM>>>(pb_ffh[0], pb_ffh[1], pb_w4[0], pb_w4[1],
        ffo_b, nullptr, p_ffo, nullptr, nullptr, NTOK, 512, 2048);
    // 12) x_out
    add_ln_kernel<false><<<NTOK,256>>>(p_x2, p_ffo, ln2_g, ln2_b, out_x);
}

// round 7
// speedup vs baseline: 3.1182x; 1.0209x over previous
#include <cuda_runtime.h>
#include <cuda_bf16.h>
#include <math.h>
#include <stdint.h>

#define TS 1024
#define TB 8
#define TE 512
#define TDH 256
#define NTOK 8192

// ---------------- fp32 scratch ----------------
__device__ __align__(16) float g_proj[(size_t)NTOK*TE];
__device__ __align__(16) float g_x1  [(size_t)NTOK*TE];
__device__ __align__(16) float g_lg  [(size_t)NTOK*128];
__device__ __align__(16) float g_x2  [(size_t)NTOK*TE];
__device__ __align__(16) float g_ffo [(size_t)NTOK*TE];
__device__ __align__(16) float g_hb  [256];

// ---------------- bf16 split scratch (hi/lo) ----------------
__device__ __align__(16) __nv_bfloat16 b_qkv [2][(size_t)NTOK*1536];
__device__ __align__(16) __nv_bfloat16 b_xin [2][(size_t)NTOK*512];
__device__ __align__(16) __nv_bfloat16 b_ao  [2][(size_t)NTOK*512];
__device__ __align__(16) __nv_bfloat16 b_lg  [2][(size_t)NTOK*128];
__device__ __align__(16) __nv_bfloat16 b_x2  [2][(size_t)NTOK*512];
__device__ __align__(16) __nv_bfloat16 b_ffh [2][(size_t)NTOK*2048];
__device__ __align__(16) __nv_bfloat16 b_hin [2][(size_t)NTOK*896];
__device__ __align__(16) __nv_bfloat16 b_lgin[2][(size_t)NTOK*768];
__device__ __align__(16) __nv_bfloat16 b_w1  [2][1536*512];
__device__ __align__(16) __nv_bfloat16 b_w2  [2][512*512];
__device__ __align__(16) __nv_bfloat16 b_uw  [2][512*128];
__device__ __align__(16) __nv_bfloat16 b_w3  [2][2048*512];
__device__ __align__(16) __nv_bfloat16 b_w4  [2][512*2048];
__device__ __align__(16) __nv_bfloat16 b_hw  [2][256*896];
__device__ __align__(16) __nv_bfloat16 b_vw  [2][128*768];

__device__ __forceinline__ float nonsat_f(float x) {
    float y = x;
#pragma unroll 1
    for (int it = 0; it < 32; ++it) {
        float y2 = y * y;
        float yn = __fdividef(0.66666668f * y * y2 + x, y2 + 1.0f);
        float d = fabsf(yn - y);
        y = yn;
        if (d <= 1e-6f) break;
    }
    return y;
}

__device__ __forceinline__ uint32_t su32(const void* p) {
    uint32_t a;
    asm("{ .reg .u64 t; cvta.to.shared.u64 t, %1; cvt.u32.u64 %0, t; }" : "=r"(a) : "l"(p));
    return a;
}
__device__ __forceinline__ void ldmx4(uint32_t* r, uint32_t addr) {
    asm volatile("ldmatrix.sync.aligned.m8n8.x4.shared.b16 {%0,%1,%2,%3}, [%4];"
        : "=r"(r[0]), "=r"(r[1]), "=r"(r[2]), "=r"(r[3]) : "r"(addr));
}
__device__ __forceinline__ void ldmx4t(uint32_t* r, uint32_t addr) {
    asm volatile("ldmatrix.sync.aligned.m8n8.x4.trans.shared.b16 {%0,%1,%2,%3}, [%4];"
        : "=r"(r[0]), "=r"(r[1]), "=r"(r[2]), "=r"(r[3]) : "r"(addr));
}
__device__ __forceinline__ void mma16816(float* c, const uint32_t* a, const uint32_t* b) {
    asm volatile(
        "mma.sync.aligned.m16n8k16.row.col.f32.bf16.bf16.f32 "
        "{%0,%1,%2,%3}, {%4,%5,%6,%7}, {%8,%9}, {%0,%1,%2,%3};\n"
        : "+f"(c[0]), "+f"(c[1]), "+f"(c[2]), "+f"(c[3])
        : "r"(a[0]), "r"(a[1]), "r"(a[2]), "r"(a[3]), "r"(b[0]), "r"(b[1]));
}
__device__ __forceinline__ uint32_t pkbf2(float lo, float hi) {
    uint32_t r;
    asm("cvt.rn.bf16x2.f32 %0, %1, %2;" : "=r"(r) : "f"(hi), "f"(lo));
    return r;
}
__device__ __forceinline__ void store_split2(__nv_bfloat16* H, __nv_bfloat16* L,
                                             size_t idx, float a, float b) {
    __nv_bfloat16 ha = __float2bfloat16(a);
    __nv_bfloat16 hb = __float2bfloat16(b);
    __nv_bfloat16 la = __float2bfloat16(a - __bfloat162float(ha));
    __nv_bfloat16 lb = __float2bfloat16(b - __bfloat162float(hb));
    union { __nv_bfloat16 x[2]; uint32_t u; } ph, pl;
    ph.x[0] = ha; ph.x[1] = hb; pl.x[0] = la; pl.x[1] = lb;
    *(uint32_t*)(H + idx) = ph.u;
    *(uint32_t*)(L + idx) = pl.u;
}

// ---------------- fp32 -> (bf16 hi, bf16 lo) split ----------------
__global__ void __launch_bounds__(256) split_kernel(
    const float* __restrict__ src, __nv_bfloat16* __restrict__ hi,
    __nv_bfloat16* __restrict__ lo, int n4)
{
    int i = blockIdx.x * 256 + threadIdx.x;
    if (i >= n4) return;
    float4 v = ((const float4*)src)[i];
    union { __nv_bfloat16 b[4]; uint2 u; } H, L;
    H.b[0] = __float2bfloat16(v.x); L.b[0] = __float2bfloat16(v.x - __bfloat162float(H.b[0]));
    H.b[1] = __float2bfloat16(v.y); L.b[1] = __float2bfloat16(v.y - __bfloat162float(H.b[1]));
    H.b[2] = __float2bfloat16(v.z); L.b[2] = __float2bfloat16(v.z - __bfloat162float(H.b[2]));
    H.b[3] = __float2bfloat16(v.w); L.b[3] = __float2bfloat16(v.w - __bfloat162float(H.b[3]));
    ((uint2*)hi)[i] = H.u;
    ((uint2*)lo)[i] = L.u;
}

// pack hidden-GEMM input: row u = [x1(perm) | hidden_prev | stack_top | 0pad], K=896
__global__ void __launch_bounds__(256) pack_hidden_in(
    const float* __restrict__ x1, const float* __restrict__ hp,
    const float* __restrict__ sp,
    __nv_bfloat16* __restrict__ H, __nv_bfloat16* __restrict__ L)
{
    int idx = blockIdx.x * 256 + threadIdx.x;
    if (idx >= NTOK * 448) return;
    int u = idx / 448, col = (idx % 448) << 1;
    float a = 0.f, b = 0.f;
    if (col < 512) {
        int tp = ((u & 1023) << 3) | (u >> 10);
        float2 v = *(const float2*)(x1 + (size_t)tp * 512 + col);
        a = v.x; b = v.y;
    } else if (col < 768) {
        float2 v = *(const float2*)(hp + (size_t)u * 256 + col - 512);
        a = v.x; b = v.y;
    } else if (col < 864) {
        float2 v = *(const float2*)(sp + (size_t)u * 4608 + col - 768);
        a = v.x; b = v.y;
    }
    store_split2(H, L, (size_t)u * 896 + col, a, b);
}

// pack hidden-GEMM weights [W_w | R_w | P_w | 0pad] (256 x 896) + summed bias
__global__ void __launch_bounds__(256) pack_hw(
    const float* __restrict__ Ww, const float* __restrict__ Rw, const float* __restrict__ Pw,
    const float* __restrict__ Wb, const float* __restrict__ Rb, const float* __restrict__ Pb,
    __nv_bfloat16* __restrict__ H, __nv_bfloat16* __restrict__ L, float* __restrict__ bsum)
{
    int idx = blockIdx.x * 256 + threadIdx.x;
    if (idx < 256) bsum[idx] = Wb[idx] + Rb[idx] + Pb[idx];
    if (idx >= 256 * 448) return;
    int n = idx / 448, col = (idx % 448) << 1;
    float a = 0.f, b = 0.f;
    if (col < 512) {
        float2 v = *(const float2*)(Ww + (size_t)n * 512 + col);
        a = v.x; b = v.y;
    } else if (col < 768) {
        float2 v = *(const float2*)(Rw + (size_t)n * 256 + col - 512);
        a = v.x; b = v.y;
    } else if (col < 864) {
        float2 v = *(const float2*)(Pw + (size_t)n * 96 + col - 768);
        a = v.x; b = v.y;
    }
    store_split2(H, L, (size_t)n * 896 + col, a, b);
}

// pack logits-GEMM input: row t = [x1(t) | hidden(perm t)], K=768
__global__ void __launch_bounds__(256) pack_logits_in(
    const float* __restrict__ x1, const float* __restrict__ hid,
    __nv_bfloat16* __restrict__ H, __nv_bfloat16* __restrict__ L)
{
    int idx = blockIdx.x * 256 + threadIdx.x;
    if (idx >= NTOK * 384) return;
    int t = idx / 384, col = (idx % 384) << 1;
    float a, b;
    if (col < 512) {
        float2 v = *(const float2*)(x1 + (size_t)t * 512 + col);
        a = v.x; b = v.y;
    } else {
        int up = ((t & 7) << 10) | (t >> 3);
        float2 v = *(const float2*)(hid + (size_t)up * 256 + col - 512);
        a = v.x; b = v.y;
    }
    store_split2(H, L, (size_t)t * 768 + col, a, b);
}

// ---------------- HMMA split GEMM (ldmatrix) ----------------
// EPI 0:+bias 1:nonsat(+bias) 2:0.5*(acc+res) 3:raw
// OUT 0:fp32 C  1:split Ch/Cl  2:both
#define T_AH 0
#define T_AL 16384
#define T_BH 32768
#define T_BL 49152
#define T_SMEM 65536

template<int EPI, int OUT>
__global__ void __launch_bounds__(256) tgemm(
    const __nv_bfloat16* __restrict__ Ah, const __nv_bfloat16* __restrict__ Al,
    const __nv_bfloat16* __restrict__ Wh, const __nv_bfloat16* __restrict__ Wl,
    const float* __restrict__ bias, const float* __restrict__ res,
    float* __restrict__ C, __nv_bfloat16* __restrict__ Ch, __nv_bfloat16* __restrict__ Cl,
    int M, int N, int K)
{
    extern __shared__ char smem[];
    const uint32_t sbase = su32(smem);
    const int tid = threadIdx.x, wid = tid >> 5, lane = tid & 31;
    const int m0 = blockIdx.y * 128, n0 = blockIdx.x * 128;
    const int g = lane >> 2, t2 = (lane & 3) << 1;
    const int wr = (wid & 1) << 6;
    const int wc = (wid >> 1) << 5;
    const int l7 = lane & 7, lr15 = lane & 15;
    const uint32_t swz = (uint32_t)(l7 << 4);
    const int aklo = (lane >> 4) << 3;
    const int bklo = ((lane >> 3) & 1) << 3;
    const uint32_t arow = (uint32_t)((wr + lr15) << 7);
    const uint32_t brow = (uint32_t)((wc + l7 + ((lane >> 4) << 3)) << 7);

    float c[4][4][4];
#pragma unroll
    for (int i = 0; i < 4; i++)
#pragma unroll
        for (int j = 0; j < 4; j++)
#pragma unroll
            for (int q = 0; q < 4; q++) c[i][j][q] = 0.f;

    const int nch = K >> 6;
    for (int ch = 0; ch < nch; ch++) {
        const int k0 = ch << 6;
#pragma unroll
        for (int t = 0; t < 4; t++) {
            int e = tid + (t << 8);
            int r = e >> 3, q = e & 7;
            uint32_t off = (uint32_t)((r << 7) + (q << 4));
            off ^= (off >> 3) & 0x70;
            const size_t ga = (size_t)(m0 + r) * K + k0 + (q << 3);
            const size_t gb = (size_t)(n0 + r) * K + k0 + (q << 3);
            *(uint4*)(smem + T_AH + off) = *(const uint4*)(Ah + ga);
            *(uint4*)(smem + T_AL + off) = *(const uint4*)(Al + ga);
            *(uint4*)(smem + T_BH + off) = *(const uint4*)(Wh + gb);
            *(uint4*)(smem + T_BL + off) = *(const uint4*)(Wl + gb);
        }
        __syncthreads();
#pragma unroll
        for (int kk = 0; kk < 64; kk += 16) {
            uint32_t bh[2][4], bl[2][4];
            const uint32_t boff = ((uint32_t)((kk + bklo) << 1)) ^ swz;
#pragma unroll
            for (int bi = 0; bi < 2; bi++) {
                ldmx4(bh[bi], sbase + T_BH + brow + (uint32_t)(bi << 11) + boff);
                ldmx4(bl[bi], sbase + T_BL + brow + (uint32_t)(bi << 11) + boff);
            }
            const uint32_t aoff = ((uint32_t)((kk + aklo) << 1)) ^ swz;
#pragma unroll
            for (int mi = 0; mi < 4; mi++) {
                uint32_t ah[4], al[4];
                ldmx4(ah, sbase + T_AH + arow + (uint32_t)(mi << 11) + aoff);
                ldmx4(al, sbase + T_AL + arow + (uint32_t)(mi << 11) + aoff);
#pragma unroll
                for (int bi = 0; bi < 2; bi++) {
                    mma16816(c[mi][2*bi],   ah, &bh[bi][0]);
                    mma16816(c[mi][2*bi],   ah, &bl[bi][0]);
                    mma16816(c[mi][2*bi],   al, &bh[bi][0]);
                    mma16816(c[mi][2*bi+1], ah, &bh[bi][2]);
                    mma16816(c[mi][2*bi+1], ah, &bl[bi][2]);
                    mma16816(c[mi][2*bi+1], al, &bh[bi][2]);
                }
            }
        }
        __syncthreads();
    }

#pragma unroll
    for (int mi = 0; mi < 4; mi++) {
#pragma unroll
        for (int ni = 0; ni < 4; ni++) {
            int row = m0 + wr + (mi << 4) + g;
            int col = n0 + wc + (ni << 3) + t2;
#pragma unroll
            for (int h = 0; h < 2; h++) {
                int rr = row + h * 8;
                float v0 = c[mi][ni][2 * h], v1 = c[mi][ni][2 * h + 1];
                if (EPI == 0) {
                    v0 += bias[col]; v1 += bias[col + 1];
                } else if (EPI == 1) {
                    v0 = nonsat_f(v0 + bias[col]); v1 = nonsat_f(v1 + bias[col + 1]);
                } else if (EPI == 2) {
                    const float2 rv = *(const float2*)(res + (size_t)rr * N + col);
                    v0 = 0.5f * (v0 + rv.x); v1 = 0.5f * (v1 + rv.y);
                }
                if (OUT == 0 || OUT == 2) {
                    float2 o; o.x = v0; o.y = v1;
                    *(float2*)(C + (size_t)rr * N + col) = o;
                }
                if (OUT == 1 || OUT == 2) {
                    store_split2(Ch, Cl, (size_t)rr * N + col, v0, v1);
                }
            }
        }
    }
}

// ---------------- HMMA flash attention (causal), split-bf16 ----------------
__global__ void __launch_bounds__(128) attn_kernel(
    const __nv_bfloat16* __restrict__ QH, const __nv_bfloat16* __restrict__ QL,
    __nv_bfloat16* __restrict__ aoh, __nv_bfloat16* __restrict__ aol)
{
    __shared__ __align__(16) char sm[49152];
    const int qt = blockIdx.x, q0 = qt << 6;
    const int b = blockIdx.y >> 3, h = blockIdx.y & 7;
    const int tid = threadIdx.x, wid = tid >> 5, lane = tid & 31;
    const int g = lane >> 2, t2 = (lane & 3) << 1;
    const uint32_t sbase = su32(sm);
    const int l7 = lane & 7, lr15 = lane & 15;
    const uint32_t swz = (uint32_t)(l7 << 4);
    const int klo8 = (lane >> 4) << 3;
    const int bk8 = ((lane >> 3) & 1) << 3;
    const int wq = wid << 4;

    const size_t qbase = ((size_t)q0 * TB + b) * 1536 + h * 64;
#pragma unroll
    for (int t = 0; t < 4; t++) {
        int e = tid + (t << 7);
        int r = e >> 3, q = e & 7;
        uint32_t off = (uint32_t)((r << 7) + (q << 4));
        off ^= (off >> 3) & 0x70;
        const size_t gs = qbase + (size_t)r * (TB * 1536) + (q << 3);
        *(uint4*)(sm + 0    + off) = *(const uint4*)(QH + gs);
        *(uint4*)(sm + 8192 + off) = *(const uint4*)(QL + gs);
    }

    float o[8][4];
#pragma unroll
    for (int i = 0; i < 8; i++)
#pragma unroll
        for (int j = 0; j < 4; j++) o[i][j] = 0.f;
    float m0 = -1e30f, m1 = -1e30f, l0 = 0.f, l1 = 0.f;

    const uint32_t aA = sbase + (uint32_t)((wq + lr15) << 7);
    const uint32_t browB = sbase + (uint32_t)((l7 + ((lane >> 4) << 3)) << 7);
    const uint32_t vrow  = sbase + (uint32_t)((l7 + (((lane >> 3) & 1) << 3)) << 7);

    for (int kt = 0; kt <= qt; kt++) {
        const int kv0 = kt << 6;
        __syncthreads();
        const size_t kbase = ((size_t)kv0 * TB + b) * 1536 + h * 64;
#pragma unroll
        for (int t = 0; t < 4; t++) {
            int e = tid + (t << 7);
            int r = e >> 3, q = e & 7;
            uint32_t off = (uint32_t)((r << 7) + (q << 4));
            off ^= (off >> 3) & 0x70;
            const size_t gk = kbase + (size_t)r * (TB * 1536) + 512 + (q << 3);
            const size_t gv = kbase + (size_t)r * (TB * 1536) + 1024 + (q << 3);
            *(uint4*)(sm + 16384 + off) = *(const uint4*)(QH + gk);
            *(uint4*)(sm + 24576 + off) = *(const uint4*)(QL + gk);
            *(uint4*)(sm + 32768 + off) = *(const uint4*)(QH + gv);
            *(uint4*)(sm + 40960 + off) = *(const uint4*)(QL + gv);
        }
        __syncthreads();

        float sc[8][4];
#pragma unroll
        for (int i = 0; i < 8; i++)
#pragma unroll
            for (int j = 0; j < 4; j++) sc[i][j] = 0.f;
#pragma unroll
        for (int kk = 0; kk < 64; kk += 16) {
            uint32_t qh[4], ql[4];
            const uint32_t aoff = ((uint32_t)((kk + klo8) << 1)) ^ swz;
            ldmx4(qh, aA + 0    + aoff);
            ldmx4(ql, aA + 8192 + aoff);
            const uint32_t boff = ((uint32_t)((kk + bk8) << 1)) ^ swz;
#pragma unroll
            for (int bi = 0; bi < 4; bi++) {
                uint32_t kh[4], kl[4];
                ldmx4(kh, browB + 16384 + (uint32_t)(bi << 11) + boff);
                ldmx4(kl, browB + 24576 + (uint32_t)(bi << 11) + boff);
                mma16816(sc[2*bi],   qh, &kh[0]);
                mma16816(sc[2*bi],   qh, &kl[0]);
                mma16816(sc[2*bi],   ql, &kh[0]);
                mma16816(sc[2*bi+1], qh, &kh[2]);
                mma16816(sc[2*bi+1], qh, &kl[2]);
                mma16816(sc[2*bi+1], ql, &kh[2]);
            }
        }

        const int r0 = q0 + wq + g, r1 = r0 + 8;
        const bool diag = (kt == qt);
        float tm0 = -1e30f, tm1 = -1e30f;
#pragma unroll
        for (int ni = 0; ni < 8; ni++) {
            const int cb = kv0 + (ni << 3) + t2;
            float s0 = sc[ni][0] * 0.125f, s1 = sc[ni][1] * 0.125f;
            float s2 = sc[ni][2] * 0.125f, s3 = sc[ni][3] * 0.125f;
            if (diag) {
                if (cb     > r0) s0 = -1e30f;
                if (cb + 1 > r0) s1 = -1e30f;
                if (cb     > r1) s2 = -1e30f;
                if (cb + 1 > r1) s3 = -1e30f;
            }
            sc[ni][0] = s0; sc[ni][1] = s1; sc[ni][2] = s2; sc[ni][3] = s3;
            tm0 = fmaxf(tm0, fmaxf(s0, s1));
            tm1 = fmaxf(tm1, fmaxf(s2, s3));
        }
        tm0 = fmaxf(tm0, __shfl_xor_sync(0xffffffffu, tm0, 1));
        tm0 = fmaxf(tm0, __shfl_xor_sync(0xffffffffu, tm0, 2));
        tm1 = fmaxf(tm1, __shfl_xor_sync(0xffffffffu, tm1, 1));
        tm1 = fmaxf(tm1, __shfl_xor_sync(0xffffffffu, tm1, 2));
        const float mn0 = fmaxf(m0, tm0), mn1 = fmaxf(m1, tm1);
        const float al0 = __expf(m0 - mn0), al1 = __expf(m1 - mn1);
        m0 = mn0; m1 = mn1;
        float ps0 = 0.f, ps1 = 0.f;
#pragma unroll
        for (int ni = 0; ni < 8; ni++) {
            float p0 = __expf(sc[ni][0] - m0), p1 = __expf(sc[ni][1] - m0);
            float p2 = __expf(sc[ni][2] - m1), p3 = __expf(sc[ni][3] - m1);
            sc[ni][0] = p0; sc[ni][1] = p1; sc[ni][2] = p2; sc[ni][3] = p3;
            ps0 += p0 + p1; ps1 += p2 + p3;
        }
        ps0 += __shfl_xor_sync(0xffffffffu, ps0, 1);
        ps0 += __shfl_xor_sync(0xffffffffu, ps0, 2);
        ps1 += __shfl_xor_sync(0xffffffffu, ps1, 1);
        ps1 += __shfl_xor_sync(0xffffffffu, ps1, 2);
        l0 = l0 * al0 + ps0;
        l1 = l1 * al1 + ps1;
#pragma unroll
        for (int ni = 0; ni < 8; ni++) {
            o[ni][0] *= al0; o[ni][1] *= al0;
            o[ni][2] *= al1; o[ni][3] *= al1;
        }

#pragma unroll
        for (int j = 0; j < 4; j++) {
            uint32_t pa[4];
            pa[0] = pkbf2(sc[2*j][0],   sc[2*j][1]);
            pa[1] = pkbf2(sc[2*j][2],   sc[2*j][3]);
            pa[2] = pkbf2(sc[2*j+1][0], sc[2*j+1][1]);
            pa[3] = pkbf2(sc[2*j+1][2], sc[2*j+1][3]);
#pragma unroll
            for (int i = 0; i < 4; i++) {
                uint32_t vh[4], vl[4];
                const uint32_t voff = (uint32_t)(j << 11) +
                    (((uint32_t)(((i << 4) + klo8) << 1)) ^ swz);
                ldmx4t(vh, vrow + 32768 + voff);
                ldmx4t(vl, vrow + 40960 + voff);
                mma16816(o[2*i],   pa, &vh[0]);
                mma16816(o[2*i],   pa, &vl[0]);
                mma16816(o[2*i+1], pa, &vh[2]);
                mma16816(o[2*i+1], pa, &vl[2]);
            }
        }
    }

    const float inv0 = __fdividef(1.f, l0), inv1 = __fdividef(1.f, l1);
    const int qg0 = q0 + wq + g;
    const size_t dst0 = ((size_t)qg0 * TB + b) * 512 + h * 64 + t2;
    const size_t dst1 = dst0 + (size_t)8 * TB * 512;
#pragma unroll
    for (int ni = 0; ni < 8; ni++) {
        const int d = ni << 3;
        store_split2(aoh, aol, dst0 + d, o[ni][0] * inv0, o[ni][1] * inv0);
        store_split2(aoh, aol, dst1 + d, o[ni][2] * inv1, o[ni][3] * inv1);
    }
}

template<bool NS>
__global__ void __launch_bounds__(256) add_ln_kernel(
    const float* __restrict__ xa, const float* __restrict__ xb,
    const float* __restrict__ g, const float* __restrict__ bl,
    float* __restrict__ out)
{
    const int t = blockIdx.x, tid = threadIdx.x;
    __shared__ float red[8];
    const size_t base = (size_t)t * TE;
    float v0 = xa[base+tid] + xb[base+tid];
    float v1 = xa[base+tid+256] + xb[base+tid+256];
    float s = v0 + v1;
#pragma unroll
    for (int o = 16; o; o >>= 1) s += __shfl_xor_sync(0xffffffffu, s, o);
    if ((tid & 31) == 0) red[tid>>5] = s;
    __syncthreads();
    if (tid == 0) { float tt=0; for (int w=0;w<8;w++) tt+=red[w]; red[0]=tt; }
    __syncthreads();
    const float mean = red[0] * (1.0f/512.0f);
    __syncthreads();
    float d0 = v0-mean, d1 = v1-mean;
    float q = d0*d0 + d1*d1;
#pragma unroll
    for (int o = 16; o; o >>= 1) q += __shfl_xor_sync(0xffffffffu, q, o);
    if ((tid & 31) == 0) red[tid>>5] = q;
    __syncthreads();
    if (tid == 0) { float tt=0; for (int w=0;w<8;w++) tt+=red[w]; red[0]=tt; }
    __syncthreads();
    const float rs = rsqrtf(red[0]*(1.0f/512.0f) + 1e-5f);
    float o0 = d0*rs*g[tid]     + bl[tid];
    float o1 = d1*rs*g[tid+256] + bl[tid+256];
    if (NS) { o0 = nonsat_f(o0); o1 = nonsat_f(o1); }
    out[base+tid] = o0;
    out[base+tid+256] = o1;
}

// softmax over 128, writes split bf16 directly
__global__ void __launch_bounds__(256) softmax128_kernel(
    const float* __restrict__ lg,
    __nv_bfloat16* __restrict__ H, __nv_bfloat16* __restrict__ L)
{
    const int t = blockIdx.x * 8 + (threadIdx.x >> 5);
    const int lane = threadIdx.x & 31;
    const float4 v0 = *((const float4*)(lg + (size_t)t * 128) + lane);
    float4 v = v0;
    float mx = fmaxf(fmaxf(v.x, v.y), fmaxf(v.z, v.w));
#pragma unroll
    for (int o = 16; o; o >>= 1) mx = fmaxf(mx, __shfl_xor_sync(0xffffffffu, mx, o));
    v.x = __expf(v.x-mx); v.y = __expf(v.y-mx); v.z = __expf(v.z-mx); v.w = __expf(v.w-mx);
    float s = v.x + v.y + v.z + v.w;
#pragma unroll
    for (int o = 16; o; o >>= 1) s += __shfl_xor_sync(0xffffffffu, s, o);
    float is = __fdividef(1.f, s);
    const size_t base = (size_t)t * 128 + (lane << 2);
    store_split2(H, L, base,     v.x * is, v.y * is);
    store_split2(H, L, base + 2, v.z * is, v.w * is);
}

__global__ void __launch_bounds__(128) stack_kernel(
    const float* __restrict__ hidden, const float* __restrict__ sp,
    const float* __restrict__ Aw, const float* __restrict__ Ab,
    const float* __restrict__ Dw, const float* __restrict__ Db,
    float* __restrict__ out)
{
    __shared__ __align__(16) float h[256];
    __shared__ __align__(16) float inp[96];
    __shared__ float ctl[3];
    const int u = blockIdx.x, tid = threadIdx.x;
    const float* hrow = hidden + (size_t)u * 256;
    h[tid] = hrow[tid]; h[tid+128] = hrow[tid+128];
    __syncthreads();
    if (tid < 96) {
        const float* w = Dw + tid * 256;
        float s = Db[tid];
        for (int k = 0; k < 256; k += 4) {
            float4 wv = *(const float4*)(w + k);
            s += wv.x*h[k] + wv.y*h[k+1] + wv.z*h[k+2] + wv.w*h[k+3];
        }
        inp[tid] = nonsat_f(s);
    } else if (tid < 99) {
        int i = tid - 96;
        const float* w = Aw + i * 256;
        float s = Ab[i];
        for (int k = 0; k < 256; k++) s += w[k]*h[k];
        ctl[i] = s;
    }
    __syncthreads();
    float mx = fmaxf(ctl[0], fmaxf(ctl[1], ctl[2]));
    float e0 = __expf(ctl[0]-mx), e1 = __expf(ctl[1]-mx), e2 = __expf(ctl[2]-mx);
    float is = __fdividef(1.f, e0+e1+e2);
    float c0 = e0*is, c1 = e1*is, c2 = e2*is;
    const float4* prev = (const float4*)(sp + (size_t)u * 4608);
    float4* dst = (float4*)(out + (size_t)u * 4608);
    const float4* inp4 = (const float4*)inp;
    for (int idx = tid; idx < 1152; idx += 128) {
        int d = idx / 24;
        float4 p = prev[idx];
        float4 up = (d == 0) ? inp4[idx] : prev[idx-24];
        float4 dn;
        if (d == 47) { dn.x=dn.y=dn.z=dn.w=0.f; } else dn = prev[idx+24];
        float4 o;
        o.x = c2*p.x + c0*up.x + c1*dn.x;
        o.y = c2*p.y + c0*up.y + c1*dn.y;
        o.z = c2*p.z + c0*up.z + c1*dn.z;
        o.w = c2*p.w + c0*up.w + c1*dn.w;
        dst[idx] = o;
    }
}

static inline void split_launch(const float* src, __nv_bfloat16* hi, __nv_bfloat16* lo, size_t n) {
    int n4 = (int)(n >> 2);
    split_kernel<<<(n4 + 255) / 256, 256>>>(src, hi, lo, n4);
}

extern "C" void kernel_launch(void* const* d_in, const int* in_sizes, int n_in,
                              void* d_out, int out_size) {
    const float* x_in = (const float*)d_in[0];
    const float* hidden_prev = (const float*)d_in[1];
    const float* stack_prev  = (const float*)d_in[2];
    const float* in_proj_w = (const float*)d_in[3];
    const float* in_proj_b = (const float*)d_in[4];
    const float* out_proj_w = (const float*)d_in[5];
    const float* out_proj_b = (const float*)d_in[6];
    const float* ln1_g = (const float*)d_in[7];
    const float* ln1_b = (const float*)d_in[8];
    const float* ln2_g = (const float*)d_in[9];
    const float* ln2_b = (const float*)d_in[10];
    const float* W_w = (const float*)d_in[11];
    const float* W_b = (const float*)d_in[12];
    const float* R_w = (const float*)d_in[13];
    const float* R_b = (const float*)d_in[14];
    const float* P_w = (const float*)d_in[15];
    const float* P_b = (const float*)d_in[16];
    const float* V_w = (const float*)d_in[17];
    const float* U_w = (const float*)d_in[18];
    const float* A_w = (const float*)d_in[19];
    const float* A_b = (const float*)d_in[20];
    const float* D_w = (const float*)d_in[21];
    const float* D_b = (const float*)d_in[22];
    const float* ffi_w = (const float*)d_in[23];
    const float* ffi_b = (const float*)d_in[24];
    const float* ffo_w = (const float*)d_in[25];
    const float* ffo_b = (const float*)d_in[26];

    static bool init_done = false;
    static float *p_proj,*p_x1,*p_lg,*p_x2,*p_ffo,*p_hb;
    static __nv_bfloat16 *pb_qkv[2],*pb_xin[2],*pb_ao[2],*pb_lg[2],*pb_x2[2],*pb_ffh[2];
    static __nv_bfloat16 *pb_hin[2],*pb_lgin[2];
    static __nv_bfloat16 *pb_w1[2],*pb_w2[2],*pb_uw[2],*pb_w3[2],*pb_w4[2],*pb_hw[2],*pb_vw[2];
    if (!init_done) {
        cudaGetSymbolAddress((void**)&p_proj, g_proj);
        cudaGetSymbolAddress((void**)&p_x1,   g_x1);
        cudaGetSymbolAddress((void**)&p_lg,   g_lg);
        cudaGetSymbolAddress((void**)&p_x2,   g_x2);
        cudaGetSymbolAddress((void**)&p_ffo,  g_ffo);
        cudaGetSymbolAddress((void**)&p_hb,   g_hb);
        __nv_bfloat16* base;
        cudaGetSymbolAddress((void**)&base, b_qkv ); pb_qkv [0]=base; pb_qkv [1]=base+(size_t)NTOK*1536;
        cudaGetSymbolAddress((void**)&base, b_xin ); pb_xin [0]=base; pb_xin [1]=base+(size_t)NTOK*512;
        cudaGetSymbolAddress((void**)&base, b_ao  ); pb_ao  [0]=base; pb_ao  [1]=base+(size_t)NTOK*512;
        cudaGetSymbolAddress((void**)&base, b_lg  ); pb_lg  [0]=base; pb_lg  [1]=base+(size_t)NTOK*128;
        cudaGetSymbolAddress((void**)&base, b_x2  ); pb_x2  [0]=base; pb_x2  [1]=base+(size_t)NTOK*512;
        cudaGetSymbolAddress((void**)&base, b_ffh ); pb_ffh [0]=base; pb_ffh [1]=base+(size_t)NTOK*2048;
        cudaGetSymbolAddress((void**)&base, b_hin ); pb_hin [0]=base; pb_hin [1]=base+(size_t)NTOK*896;
        cudaGetSymbolAddress((void**)&base, b_lgin); pb_lgin[0]=base; pb_lgin[1]=base+(size_t)NTOK*768;
        cudaGetSymbolAddress((void**)&base, b_w1  ); pb_w1  [0]=base; pb_w1  [1]=base+(size_t)1536*512;
        cudaGetSymbolAddress((void**)&base, b_w2  ); pb_w2  [0]=base; pb_w2  [1]=base+(size_t)512*512;
        cudaGetSymbolAddress((void**)&base, b_uw  ); pb_uw  [0]=base; pb_uw  [1]=base+(size_t)512*128;
        cudaGetSymbolAddress((void**)&base, b_w3  ); pb_w3  [0]=base; pb_w3  [1]=base+(size_t)2048*512;
        cudaGetSymbolAddress((void**)&base, b_w4  ); pb_w4  [0]=base; pb_w4  [1]=base+(size_t)512*2048;
        cudaGetSymbolAddress((void**)&base, b_hw  ); pb_hw  [0]=base; pb_hw  [1]=base+(size_t)256*896;
        cudaGetSymbolAddress((void**)&base, b_vw  ); pb_vw  [0]=base; pb_vw  [1]=base+(size_t)128*768;
        cudaFuncSetAttribute(tgemm<0,0>, cudaFuncAttributeMaxDynamicSharedMemorySize, T_SMEM);
        cudaFuncSetAttribute(tgemm<0,1>, cudaFuncAttributeMaxDynamicSharedMemorySize, T_SMEM);
        cudaFuncSetAttribute(tgemm<1,0>, cudaFuncAttributeMaxDynamicSharedMemorySize, T_SMEM);
        cudaFuncSetAttribute(tgemm<1,1>, cudaFuncAttributeMaxDynamicSharedMemorySize, T_SMEM);
        cudaFuncSetAttribute(tgemm<2,2>, cudaFuncAttributeMaxDynamicSharedMemorySize, T_SMEM);
        cudaFuncSetAttribute(tgemm<3,0>, cudaFuncAttributeMaxDynamicSharedMemorySize, T_SMEM);
        init_done = true;
    }

    float* out_x = (float*)d_out;
    float* out_hidden = out_x + (size_t)NTOK * TE;
    float* out_stack  = out_hidden + (size_t)NTOK * TDH;

    // splits + weight packs
    split_launch(in_proj_w, pb_w1[0], pb_w1[1], (size_t)1536*512);
    split_launch(out_proj_w, pb_w2[0], pb_w2[1], (size_t)512*512);
    split_launch(U_w, pb_uw[0], pb_uw[1], (size_t)512*128);
    split_launch(ffi_w, pb_w3[0], pb_w3[1], (size_t)2048*512);
    split_launch(ffo_w, pb_w4[0], pb_w4[1], (size_t)512*2048);
    split_launch(V_w, pb_vw[0], pb_vw[1], (size_t)128*768);
    pack_hw<<<(256*448 + 255)/256, 256>>>(W_w, R_w, P_w, W_b, R_b, P_b,
                                          pb_hw[0], pb_hw[1], p_hb);
    split_launch(x_in, pb_xin[0], pb_xin[1], (size_t)NTOK*512);

    // 1) qkv (split out)
    tgemm<0,1><<<dim3(12,64),256,T_SMEM>>>(pb_xin[0], pb_xin[1], pb_w1[0], pb_w1[1],
        in_proj_b, nullptr, nullptr, pb_qkv[0], pb_qkv[1], NTOK, 1536, 512);
    // 2) flash attention
    attn_kernel<<<dim3(16,64),128>>>(pb_qkv[0], pb_qkv[1], pb_ao[0], pb_ao[1]);
    // 3) out projection
    tgemm<0,0><<<dim3(4,64),256,T_SMEM>>>(pb_ao[0], pb_ao[1], pb_w2[0], pb_w2[1],
        out_proj_b, nullptr, p_proj, nullptr, nullptr, NTOK, 512, 512);
    // 4) x1 = nonsat(LN(x_in + proj))
    add_ln_kernel<true><<<NTOK,256>>>(x_in, p_proj, ln1_g, ln1_b, p_x1);
    // 5) hidden via HMMA: pack input then tgemm
    pack_hidden_in<<<(NTOK*448 + 255)/256, 256>>>(p_x1, hidden_prev, stack_prev,
                                                  pb_hin[0], pb_hin[1]);
    tgemm<1,0><<<dim3(2,64),256,T_SMEM>>>(pb_hin[0], pb_hin[1], pb_hw[0], pb_hw[1],
        p_hb, nullptr, out_hidden, nullptr, nullptr, NTOK, 256, 896);
    // 6) logits via HMMA
    pack_logits_in<<<(NTOK*384 + 255)/256, 256>>>(p_x1, out_hidden, pb_lgin[0], pb_lgin[1]);
    tgemm<3,0><<<dim3(1,64),256,T_SMEM>>>(pb_lgin[0], pb_lgin[1], pb_vw[0], pb_vw[1],
        nullptr, nullptr, p_lg, nullptr, nullptr, NTOK, 128, 768);
    // 7) softmax (split out)
    softmax128_kernel<<<NTOK/8,256>>>(p_lg, pb_lg[0], pb_lg[1]);
    // 8) x2 = 0.5*(x1 + sm @ U_w.T)  (fp32 + split out)
    tgemm<2,2><<<dim3(4,64),256,T_SMEM>>>(pb_lg[0], pb_lg[1], pb_uw[0], pb_uw[1],
        nullptr, p_x1, p_x2, pb_x2[0], pb_x2[1], NTOK, 512, 128);
    // 9) stack
    stack_kernel<<<NTOK,128>>>(out_hidden, stack_prev, A_w, A_b, D_w, D_b, out_stack);
    // 10) ff hidden (split out)
    tgemm<1,1><<<dim3(16,64),256,T_SMEM>>>(pb_x2[0], pb_x2[1], pb_w3[0], pb_w3[1],
        ffi_b, nullptr, nullptr, pb_ffh[0], pb_ffh[1], NTOK, 2048, 512);
    // 11) ff out
    tgemm<0,0><<<dim3(4,64),256,T_SMEM>>>(pb_ffh[0], pb_ffh[1], pb_w4[0], pb_w4[1],
        ffo_b, nullptr, p_ffo, nullptr, nullptr, NTOK, 512, 2048);
    // 12) x_out
    add_ln_kernel<false><<<NTOK,256>>>(p_x2, p_ffo, ln2_g, ln2_b, out_x);
}

// round 8
// speedup vs baseline: 4.0172x; 1.2883x over previous
#include <cuda_runtime.h>
#include <cuda_bf16.h>
#include <math.h>
#include <stdint.h>

#define TS 1024
#define TB 8
#define TE 512
#define TDH 256
#define NTOK 8192

// ---------------- fp32 scratch ----------------
__device__ __align__(16) float g_proj[(size_t)NTOK*TE];
__device__ __align__(16) float g_x1  [(size_t)NTOK*TE];
__device__ __align__(16) float g_lg  [(size_t)NTOK*128];
__device__ __align__(16) float g_x2  [(size_t)NTOK*TE];
__device__ __align__(16) float g_ffo [(size_t)NTOK*TE];
__device__ __align__(16) float g_hb  [256];

// ---------------- bf16 split scratch (hi/lo) ----------------
__device__ __align__(16) __nv_bfloat16 b_qkv [2][(size_t)NTOK*1536];
__device__ __align__(16) __nv_bfloat16 b_xin [2][(size_t)NTOK*512];
__device__ __align__(16) __nv_bfloat16 b_ao  [2][(size_t)NTOK*512];
__device__ __align__(16) __nv_bfloat16 b_lg  [2][(size_t)NTOK*128];
__device__ __align__(16) __nv_bfloat16 b_x2  [2][(size_t)NTOK*512];
__device__ __align__(16) __nv_bfloat16 b_ffh [2][(size_t)NTOK*2048];
__device__ __align__(16) __nv_bfloat16 b_hin [2][(size_t)NTOK*896];
__device__ __align__(16) __nv_bfloat16 b_lgin[2][(size_t)NTOK*768];
__device__ __align__(16) __nv_bfloat16 b_w1  [2][1536*512];
__device__ __align__(16) __nv_bfloat16 b_w2  [2][512*512];
__device__ __align__(16) __nv_bfloat16 b_uw  [2][512*128];
__device__ __align__(16) __nv_bfloat16 b_w3  [2][2048*512];
__device__ __align__(16) __nv_bfloat16 b_w4  [2][512*2048];
__device__ __align__(16) __nv_bfloat16 b_hw  [2][256*896];
__device__ __align__(16) __nv_bfloat16 b_vw  [2][128*768];

__device__ __forceinline__ float nonsat_f(float x) {
    float y = x;
#pragma unroll 1
    for (int it = 0; it < 32; ++it) {
        float y2 = y * y;
        float yn = __fdividef(0.66666668f * y * y2 + x, y2 + 1.0f);
        float d = fabsf(yn - y);
        y = yn;
        if (d <= 1e-6f) break;
    }
    return y;
}

__device__ __forceinline__ uint32_t su32(const void* p) {
    uint32_t a;
    asm("{ .reg .u64 t; cvta.to.shared.u64 t, %1; cvt.u32.u64 %0, t; }" : "=r"(a) : "l"(p));
    return a;
}
__device__ __forceinline__ void cp16(uint32_t s, const void* g) {
    asm volatile("cp.async.cg.shared.global [%0], [%1], 16;"
                 :: "r"(s), "l"(__cvta_generic_to_global(g)) : "memory");
}
__device__ __forceinline__ void cp_commit() {
    asm volatile("cp.async.commit_group;" ::: "memory");
}
template<int N> __device__ __forceinline__ void cp_wait() {
    asm volatile("cp.async.wait_group %0;" :: "n"(N) : "memory");
}
__device__ __forceinline__ void ldmx4(uint32_t* r, uint32_t addr) {
    asm volatile("ldmatrix.sync.aligned.m8n8.x4.shared.b16 {%0,%1,%2,%3}, [%4];"
        : "=r"(r[0]), "=r"(r[1]), "=r"(r[2]), "=r"(r[3]) : "r"(addr));
}
__device__ __forceinline__ void ldmx4t(uint32_t* r, uint32_t addr) {
    asm volatile("ldmatrix.sync.aligned.m8n8.x4.trans.shared.b16 {%0,%1,%2,%3}, [%4];"
        : "=r"(r[0]), "=r"(r[1]), "=r"(r[2]), "=r"(r[3]) : "r"(addr));
}
__device__ __forceinline__ void mma16816(float* c, const uint32_t* a, const uint32_t* b) {
    asm volatile(
        "mma.sync.aligned.m16n8k16.row.col.f32.bf16.bf16.f32 "
        "{%0,%1,%2,%3}, {%4,%5,%6,%7}, {%8,%9}, {%0,%1,%2,%3};\n"
        : "+f"(c[0]), "+f"(c[1]), "+f"(c[2]), "+f"(c[3])
        : "r"(a[0]), "r"(a[1]), "r"(a[2]), "r"(a[3]), "r"(b[0]), "r"(b[1]));
}
__device__ __forceinline__ uint32_t pkbf2(float lo, float hi) {
    uint32_t r;
    asm("cvt.rn.bf16x2.f32 %0, %1, %2;" : "=r"(r) : "f"(hi), "f"(lo));
    return r;
}
__device__ __forceinline__ void store_split2(__nv_bfloat16* H, __nv_bfloat16* L,
                                             size_t idx, float a, float b) {
    __nv_bfloat16 ha = __float2bfloat16(a);
    __nv_bfloat16 hb = __float2bfloat16(b);
    __nv_bfloat16 la = __float2bfloat16(a - __bfloat162float(ha));
    __nv_bfloat16 lb = __float2bfloat16(b - __bfloat162float(hb));
    union { __nv_bfloat16 x[2]; uint32_t u; } ph, pl;
    ph.x[0] = ha; ph.x[1] = hb; pl.x[0] = la; pl.x[1] = lb;
    *(uint32_t*)(H + idx) = ph.u;
    *(uint32_t*)(L + idx) = pl.u;
}

// ---------------- fp32 -> (bf16 hi, bf16 lo) split ----------------
__global__ void __launch_bounds__(256) split_kernel(
    const float* __restrict__ src, __nv_bfloat16* __restrict__ hi,
    __nv_bfloat16* __restrict__ lo, int n4)
{
    int i = blockIdx.x * 256 + threadIdx.x;
    if (i >= n4) return;
    float4 v = ((const float4*)src)[i];
    union { __nv_bfloat16 b[4]; uint2 u; } H, L;
    H.b[0] = __float2bfloat16(v.x); L.b[0] = __float2bfloat16(v.x - __bfloat162float(H.b[0]));
    H.b[1] = __float2bfloat16(v.y); L.b[1] = __float2bfloat16(v.y - __bfloat162float(H.b[1]));
    H.b[2] = __float2bfloat16(v.z); L.b[2] = __float2bfloat16(v.z - __bfloat162float(H.b[2]));
    H.b[3] = __float2bfloat16(v.w); L.b[3] = __float2bfloat16(v.w - __bfloat162float(H.b[3]));
    ((uint2*)hi)[i] = H.u;
    ((uint2*)lo)[i] = L.u;
}

// pack hidden-GEMM input: row u = [x1(perm) | hidden_prev | stack_top | 0pad], K=896
__global__ void __launch_bounds__(256) pack_hidden_in(
    const float* __restrict__ x1, const float* __restrict__ hp,
    const float* __restrict__ sp,
    __nv_bfloat16* __restrict__ H, __nv_bfloat16* __restrict__ L)
{
    int idx = blockIdx.x * 256 + threadIdx.x;
    if (idx >= NTOK * 448) return;
    int u = idx / 448, col = (idx % 448) << 1;
    float a = 0.f, b = 0.f;
    if (col < 512) {
        int tp = ((u & 1023) << 3) | (u >> 10);
        float2 v = *(const float2*)(x1 + (size_t)tp * 512 + col);
        a = v.x; b = v.y;
    } else if (col < 768) {
        float2 v = *(const float2*)(hp + (size_t)u * 256 + col - 512);
        a = v.x; b = v.y;
    } else if (col < 864) {
        float2 v = *(const float2*)(sp + (size_t)u * 4608 + col - 768);
        a = v.x; b = v.y;
    }
    store_split2(H, L, (size_t)u * 896 + col, a, b);
}

// pack hidden-GEMM weights [W_w | R_w | P_w | 0pad] (256 x 896) + summed bias
__global__ void __launch_bounds__(256) pack_hw(
    const float* __restrict__ Ww, const float* __restrict__ Rw, const float* __restrict__ Pw,
    const float* __restrict__ Wb, const float* __restrict__ Rb, const float* __restrict__ Pb,
    __nv_bfloat16* __restrict__ H, __nv_bfloat16* __restrict__ L, float* __restrict__ bsum)
{
    int idx = blockIdx.x * 256 + threadIdx.x;
    if (idx < 256) bsum[idx] = Wb[idx] + Rb[idx] + Pb[idx];
    if (idx >= 256 * 448) return;
    int n = idx / 448, col = (idx % 448) << 1;
    float a = 0.f, b = 0.f;
    if (col < 512) {
        float2 v = *(const float2*)(Ww + (size_t)n * 512 + col);
        a = v.x; b = v.y;
    } else if (col < 768) {
        float2 v = *(const float2*)(Rw + (size_t)n * 256 + col - 512);
        a = v.x; b = v.y;
    } else if (col < 864) {
        float2 v = *(const float2*)(Pw + (size_t)n * 96 + col - 768);
        a = v.x; b = v.y;
    }
    store_split2(H, L, (size_t)n * 896 + col, a, b);
}

// pack logits-GEMM input: row t = [x1(t) | hidden(perm t)], K=768
__global__ void __launch_bounds__(256) pack_logits_in(
    const float* __restrict__ x1, const float* __restrict__ hid,
    __nv_bfloat16* __restrict__ H, __nv_bfloat16* __restrict__ L)
{
    int idx = blockIdx.x * 256 + threadIdx.x;
    if (idx >= NTOK * 384) return;
    int t = idx / 384, col = (idx % 384) << 1;
    float a, b;
    if (col < 512) {
        float2 v = *(const float2*)(x1 + (size_t)t * 512 + col);
        a = v.x; b = v.y;
    } else {
        int up = ((t & 7) << 10) | (t >> 3);
        float2 v = *(const float2*)(hid + (size_t)up * 256 + col - 512);
        a = v.x; b = v.y;
    }
    store_split2(H, L, (size_t)t * 768 + col, a, b);
}

// ---------------- HMMA split GEMM, cp.async double-buffered ----------------
// EPI 0:+bias 1:nonsat(+bias) 2:0.5*(acc+res) 3:raw ; OUT 0:fp32 1:split 2:both
#define T_AH 0
#define T_AL 16384
#define T_BH 32768
#define T_BL 49152
#define T_STAGE 65536
#define T_SMEM  131072

template<int EPI, int OUT>
__global__ void __launch_bounds__(256) tgemm(
    const __nv_bfloat16* __restrict__ Ah, const __nv_bfloat16* __restrict__ Al,
    const __nv_bfloat16* __restrict__ Wh, const __nv_bfloat16* __restrict__ Wl,
    const float* __restrict__ bias, const float* __restrict__ res,
    float* __restrict__ C, __nv_bfloat16* __restrict__ Ch, __nv_bfloat16* __restrict__ Cl,
    int M, int N, int K)
{
    extern __shared__ char smem[];
    const uint32_t sbase = su32(smem);
    const int tid = threadIdx.x, wid = tid >> 5, lane = tid & 31;
    const int m0 = blockIdx.y * 128, n0 = blockIdx.x * 128;
    const int g = lane >> 2, t2 = (lane & 3) << 1;
    const int wr = (wid & 1) << 6;
    const int wc = (wid >> 1) << 5;
    const int l7 = lane & 7, lr15 = lane & 15;
    const uint32_t swz = (uint32_t)(l7 << 4);
    const int aklo = (lane >> 4) << 3;
    const int bklo = ((lane >> 3) & 1) << 3;
    const uint32_t arow = (uint32_t)((wr + lr15) << 7);
    const uint32_t brow = (uint32_t)((wc + l7 + ((lane >> 4) << 3)) << 7);

    uint32_t soff[4]; size_t gaoff[4], gboff[4];
#pragma unroll
    for (int t = 0; t < 4; t++) {
        int e = tid + (t << 8);
        int r = e >> 3, q = e & 7;
        uint32_t off = (uint32_t)((r << 7) + (q << 4));
        off ^= (off >> 3) & 0x70;
        soff[t] = off;
        gaoff[t] = (size_t)(m0 + r) * K + (q << 3);
        gboff[t] = (size_t)(n0 + r) * K + (q << 3);
    }

    float c[4][4][4];
#pragma unroll
    for (int i = 0; i < 4; i++)
#pragma unroll
        for (int j = 0; j < 4; j++)
#pragma unroll
            for (int q = 0; q < 4; q++) c[i][j][q] = 0.f;

    const int nch = K >> 6;

#define ISSUE_CHUNK(CH, BUF) do { \
    const int k0_ = (CH) << 6; \
    const uint32_t sb_ = sbase + (BUF) * T_STAGE; \
    for (int t_ = 0; t_ < 4; t_++) { \
        cp16(sb_ + T_AH + soff[t_], Ah + gaoff[t_] + k0_); \
        cp16(sb_ + T_AL + soff[t_], Al + gaoff[t_] + k0_); \
        cp16(sb_ + T_BH + soff[t_], Wh + gboff[t_] + k0_); \
        cp16(sb_ + T_BL + soff[t_], Wl + gboff[t_] + k0_); \
    } \
    cp_commit(); \
} while (0)

    ISSUE_CHUNK(0, 0);
    for (int ch = 0; ch < nch; ch++) {
        if (ch + 1 < nch) { ISSUE_CHUNK(ch + 1, (ch + 1) & 1); cp_wait<1>(); }
        else cp_wait<0>();
        __syncthreads();
        const uint32_t bb = sbase + (ch & 1) * T_STAGE;
#pragma unroll
        for (int kk = 0; kk < 64; kk += 16) {
            uint32_t bh[2][4], bl[2][4];
            const uint32_t boff = ((uint32_t)((kk + bklo) << 1)) ^ swz;
#pragma unroll
            for (int bi = 0; bi < 2; bi++) {
                ldmx4(bh[bi], bb + T_BH + brow + (uint32_t)(bi << 11) + boff);
                ldmx4(bl[bi], bb + T_BL + brow + (uint32_t)(bi << 11) + boff);
            }
            const uint32_t aoff = ((uint32_t)((kk + aklo) << 1)) ^ swz;
#pragma unroll
            for (int mi = 0; mi < 4; mi++) {
                uint32_t ah[4], al[4];
                ldmx4(ah, bb + T_AH + arow + (uint32_t)(mi << 11) + aoff);
                ldmx4(al, bb + T_AL + arow + (uint32_t)(mi << 11) + aoff);
#pragma unroll
                for (int bi = 0; bi < 2; bi++) {
                    mma16816(c[mi][2*bi],   ah, &bh[bi][0]);
                    mma16816(c[mi][2*bi],   ah, &bl[bi][0]);
                    mma16816(c[mi][2*bi],   al, &bh[bi][0]);
                    mma16816(c[mi][2*bi+1], ah, &bh[bi][2]);
                    mma16816(c[mi][2*bi+1], ah, &bl[bi][2]);
                    mma16816(c[mi][2*bi+1], al, &bh[bi][2]);
                }
            }
        }
        __syncthreads();
    }
#undef ISSUE_CHUNK

#pragma unroll
    for (int mi = 0; mi < 4; mi++) {
#pragma unroll
        for (int ni = 0; ni < 4; ni++) {
            int row = m0 + wr + (mi << 4) + g;
            int col = n0 + wc + (ni << 3) + t2;
#pragma unroll
            for (int h = 0; h < 2; h++) {
                int rr = row + h * 8;
                float v0 = c[mi][ni][2 * h], v1 = c[mi][ni][2 * h + 1];
                if (EPI == 0) {
                    v0 += bias[col]; v1 += bias[col + 1];
                } else if (EPI == 1) {
                    v0 = nonsat_f(v0 + bias[col]); v1 = nonsat_f(v1 + bias[col + 1]);
                } else if (EPI == 2) {
                    const float2 rv = *(const float2*)(res + (size_t)rr * N + col);
                    v0 = 0.5f * (v0 + rv.x); v1 = 0.5f * (v1 + rv.y);
                }
                if (OUT == 0 || OUT == 2) {
                    float2 o; o.x = v0; o.y = v1;
                    *(float2*)(C + (size_t)rr * N + col) = o;
                }
                if (OUT == 1 || OUT == 2) {
                    store_split2(Ch, Cl, (size_t)rr * N + col, v0, v1);
                }
            }
        }
    }
}

// ---------------- HMMA flash attention, cp.async double-buffered ----------------
// smem: QH 0, QL 8192; stage s at 16384 + s*32768 {KH+0, KL+8192, VH+16384, VL+24576}
#define A_SMEM 81920

__global__ void __launch_bounds__(128) attn_kernel(
    const __nv_bfloat16* __restrict__ QH, const __nv_bfloat16* __restrict__ QL,
    __nv_bfloat16* __restrict__ aoh, __nv_bfloat16* __restrict__ aol)
{
    extern __shared__ char sm[];
    const int qt = blockIdx.x, q0 = qt << 6;
    const int b = blockIdx.y >> 3, h = blockIdx.y & 7;
    const int tid = threadIdx.x, wid = tid >> 5, lane = tid & 31;
    const int g = lane >> 2, t2 = (lane & 3) << 1;
    const uint32_t sbase = su32(sm);
    const int l7 = lane & 7, lr15 = lane & 15;
    const uint32_t swz = (uint32_t)(l7 << 4);
    const int klo8 = (lane >> 4) << 3;
    const int bk8 = ((lane >> 3) & 1) << 3;
    const int wq = wid << 4;

    uint32_t soff[4]; int srow[4], sq8[4];
#pragma unroll
    for (int t = 0; t < 4; t++) {
        int e = tid + (t << 7);
        int r = e >> 3, q = e & 7;
        uint32_t off = (uint32_t)((r << 7) + (q << 4));
        off ^= (off >> 3) & 0x70;
        soff[t] = off; srow[t] = r; sq8[t] = q << 3;
    }

    // issue Q + KV stage0 as group 0
    const size_t qbase = ((size_t)q0 * TB + b) * 1536 + h * 64;
#pragma unroll
    for (int t = 0; t < 4; t++) {
        const size_t gs = qbase + (size_t)srow[t] * (TB * 1536) + sq8[t];
        cp16(sbase + 0    + soff[t], QH + gs);
        cp16(sbase + 8192 + soff[t], QL + gs);
    }
#define ISSUE_KV(KT, BUF) do { \
    const size_t kb_ = ((size_t)((KT) << 6) * TB + b) * 1536 + h * 64; \
    const uint32_t st_ = sbase + 16384 + (BUF) * 32768; \
    for (int t_ = 0; t_ < 4; t_++) { \
        const size_t gk_ = kb_ + (size_t)srow[t_] * (TB * 1536) + 512 + sq8[t_]; \
        const size_t gv_ = kb_ + (size_t)srow[t_] * (TB * 1536) + 1024 + sq8[t_]; \
        cp16(st_ + 0     + soff[t_], QH + gk_); \
        cp16(st_ + 8192  + soff[t_], QL + gk_); \
        cp16(st_ + 16384 + soff[t_], QH + gv_); \
        cp16(st_ + 24576 + soff[t_], QL + gv_); \
    } \
    cp_commit(); \
} while (0)
    ISSUE_KV(0, 0);

    float o[8][4];
#pragma unroll
    for (int i = 0; i < 8; i++)
#pragma unroll
        for (int j = 0; j < 4; j++) o[i][j] = 0.f;
    float m0 = -1e30f, m1 = -1e30f, l0 = 0.f, l1 = 0.f;

    const uint32_t aA = sbase + (uint32_t)((wq + lr15) << 7);
    const uint32_t brel = (uint32_t)((l7 + ((lane >> 4) << 3)) << 7);
    const uint32_t vrel = (uint32_t)((l7 + (((lane >> 3) & 1) << 3)) << 7);

    for (int kt = 0; kt <= qt; kt++) {
        const int kv0 = kt << 6;
        if (kt + 1 <= qt) { ISSUE_KV(kt + 1, (kt + 1) & 1); cp_wait<1>(); }
        else cp_wait<0>();
        __syncthreads();
        const uint32_t st = sbase + 16384 + (kt & 1) * 32768;

        float sc[8][4];
#pragma unroll
        for (int i = 0; i < 8; i++)
#pragma unroll
            for (int j = 0; j < 4; j++) sc[i][j] = 0.f;
#pragma unroll
        for (int kk = 0; kk < 64; kk += 16) {
            uint32_t qh[4], ql[4];
            const uint32_t aoff = ((uint32_t)((kk + klo8) << 1)) ^ swz;
            ldmx4(qh, aA + 0    + aoff);
            ldmx4(ql, aA + 8192 + aoff);
            const uint32_t boff = ((uint32_t)((kk + bk8) << 1)) ^ swz;
#pragma unroll
            for (int bi = 0; bi < 4; bi++) {
                uint32_t kh[4], kl[4];
                ldmx4(kh, st + 0    + brel + (uint32_t)(bi << 11) + boff);
                ldmx4(kl, st + 8192 + brel + (uint32_t)(bi << 11) + boff);
                mma16816(sc[2*bi],   qh, &kh[0]);
                mma16816(sc[2*bi],   qh, &kl[0]);
                mma16816(sc[2*bi],   ql, &kh[0]);
                mma16816(sc[2*bi+1], qh, &kh[2]);
                mma16816(sc[2*bi+1], qh, &kl[2]);
                mma16816(sc[2*bi+1], ql, &kh[2]);
            }
        }

        const int r0 = q0 + wq + g, r1 = r0 + 8;
        const bool diag = (kt == qt);
        float tm0 = -1e30f, tm1 = -1e30f;
#pragma unroll
        for (int ni = 0; ni < 8; ni++) {
            const int cb = kv0 + (ni << 3) + t2;
            float s0 = sc[ni][0] * 0.125f, s1 = sc[ni][1] * 0.125f;
            float s2 = sc[ni][2] * 0.125f, s3 = sc[ni][3] * 0.125f;
            if (diag) {
                if (cb     > r0) s0 = -1e30f;
                if (cb + 1 > r0) s1 = -1e30f;
                if (cb     > r1) s2 = -1e30f;
                if (cb + 1 > r1) s3 = -1e30f;
            }
            sc[ni][0] = s0; sc[ni][1] = s1; sc[ni][2] = s2; sc[ni][3] = s3;
            tm0 = fmaxf(tm0, fmaxf(s0, s1));
            tm1 = fmaxf(tm1, fmaxf(s2, s3));
        }
        tm0 = fmaxf(tm0, __shfl_xor_sync(0xffffffffu, tm0, 1));
        tm0 = fmaxf(tm0, __shfl_xor_sync(0xffffffffu, tm0, 2));
        tm1 = fmaxf(tm1, __shfl_xor_sync(0xffffffffu, tm1, 1));
        tm1 = fmaxf(tm1, __shfl_xor_sync(0xffffffffu, tm1, 2));
        const float mn0 = fmaxf(m0, tm0), mn1 = fmaxf(m1, tm1);
        const float al0 = __expf(m0 - mn0), al1 = __expf(m1 - mn1);
        m0 = mn0; m1 = mn1;
        float ps0 = 0.f, ps1 = 0.f;
#pragma unroll
        for (int ni = 0; ni < 8; ni++) {
            float p0 = __expf(sc[ni][0] - m0), p1 = __expf(sc[ni][1] - m0);
            float p2 = __expf(sc[ni][2] - m1), p3 = __expf(sc[ni][3] - m1);
            sc[ni][0] = p0; sc[ni][1] = p1; sc[ni][2] = p2; sc[ni][3] = p3;
            ps0 += p0 + p1; ps1 += p2 + p3;
        }
        ps0 += __shfl_xor_sync(0xffffffffu, ps0, 1);
        ps0 += __shfl_xor_sync(0xffffffffu, ps0, 2);
        ps1 += __shfl_xor_sync(0xffffffffu, ps1, 1);
        ps1 += __shfl_xor_sync(0xffffffffu, ps1, 2);
        l0 = l0 * al0 + ps0;
        l1 = l1 * al1 + ps1;
#pragma unroll
        for (int ni = 0; ni < 8; ni++) {
            o[ni][0] *= al0; o[ni][1] *= al0;
            o[ni][2] *= al1; o[ni][3] *= al1;
        }

#pragma unroll
        for (int j = 0; j < 4; j++) {
            uint32_t pa[4];
            pa[0] = pkbf2(sc[2*j][0],   sc[2*j][1]);
            pa[1] = pkbf2(sc[2*j][2],   sc[2*j][3]);
            pa[2] = pkbf2(sc[2*j+1][0], sc[2*j+1][1]);
            pa[3] = pkbf2(sc[2*j+1][2], sc[2*j+1][3]);
#pragma unroll
            for (int i = 0; i < 4; i++) {
                uint32_t vh[4], vl[4];
                const uint32_t voff = (uint32_t)(j << 11) +
                    (((uint32_t)(((i << 4) + klo8) << 1)) ^ swz);
                ldmx4t(vh, st + 16384 + vrel + voff);
                ldmx4t(vl, st + 24576 + vrel + voff);
                mma16816(o[2*i],   pa, &vh[0]);
                mma16816(o[2*i],   pa, &vl[0]);
                mma16816(o[2*i+1], pa, &vh[2]);
                mma16816(o[2*i+1], pa, &vl[2]);
            }
        }
        __syncthreads();
    }
#undef ISSUE_KV

    const float inv0 = __fdividef(1.f, l0), inv1 = __fdividef(1.f, l1);
    const int qg0 = q0 + wq + g;
    const size_t dst0 = ((size_t)qg0 * TB + b) * 512 + h * 64 + t2;
    const size_t dst1 = dst0 + (size_t)8 * TB * 512;
#pragma unroll
    for (int ni = 0; ni < 8; ni++) {
        const int d = ni << 3;
        store_split2(aoh, aol, dst0 + d, o[ni][0] * inv0, o[ni][1] * inv0);
        store_split2(aoh, aol, dst1 + d, o[ni][2] * inv1, o[ni][3] * inv1);
    }
}

template<bool NS>
__global__ void __launch_bounds__(256) add_ln_kernel(
    const float* __restrict__ xa, const float* __restrict__ xb,
    const float* __restrict__ g, const float* __restrict__ bl,
    float* __restrict__ out)
{
    const int t = blockIdx.x, tid = threadIdx.x;
    __shared__ float red[8];
    const size_t base = (size_t)t * TE;
    float v0 = xa[base+tid] + xb[base+tid];
    float v1 = xa[base+tid+256] + xb[base+tid+256];
    float s = v0 + v1;
#pragma unroll
    for (int o = 16; o; o >>= 1) s += __shfl_xor_sync(0xffffffffu, s, o);
    if ((tid & 31) == 0) red[tid>>5] = s;
    __syncthreads();
    if (tid == 0) { float tt=0; for (int w=0;w<8;w++) tt+=red[w]; red[0]=tt; }
    __syncthreads();
    const float mean = red[0] * (1.0f/512.0f);
    __syncthreads();
    float d0 = v0-mean, d1 = v1-mean;
    float q = d0*d0 + d1*d1;
#pragma unroll
    for (int o = 16; o; o >>= 1) q += __shfl_xor_sync(0xffffffffu, q, o);
    if ((tid & 31) == 0) red[tid>>5] = q;
    __syncthreads();
    if (tid == 0) { float tt=0; for (int w=0;w<8;w++) tt+=red[w]; red[0]=tt; }
    __syncthreads();
    const float rs = rsqrtf(red[0]*(1.0f/512.0f) + 1e-5f);
    float o0 = d0*rs*g[tid]     + bl[tid];
    float o1 = d1*rs*g[tid+256] + bl[tid+256];
    if (NS) { o0 = nonsat_f(o0); o1 = nonsat_f(o1); }
    out[base+tid] = o0;
    out[base+tid+256] = o1;
}

// softmax over 128, writes split bf16 directly
__global__ void __launch_bounds__(256) softmax128_kernel(
    const float* __restrict__ lg,
    __nv_bfloat16* __restrict__ H, __nv_bfloat16* __restrict__ L)
{
    const int t = blockIdx.x * 8 + (threadIdx.x >> 5);
    const int lane = threadIdx.x & 31;
    float4 v = *((const float4*)(lg + (size_t)t * 128) + lane);
    float mx = fmaxf(fmaxf(v.x, v.y), fmaxf(v.z, v.w));
#pragma unroll
    for (int o = 16; o; o >>= 1) mx = fmaxf(mx, __shfl_xor_sync(0xffffffffu, mx, o));
    v.x = __expf(v.x-mx); v.y = __expf(v.y-mx); v.z = __expf(v.z-mx); v.w = __expf(v.w-mx);
    float s = v.x + v.y + v.z + v.w;
#pragma unroll
    for (int o = 16; o; o >>= 1) s += __shfl_xor_sync(0xffffffffu, s, o);
    float is = __fdividef(1.f, s);
    const size_t base = (size_t)t * 128 + (lane << 2);
    store_split2(H, L, base,     v.x * is, v.y * is);
    store_split2(H, L, base + 2, v.z * is, v.w * is);
}

__global__ void __launch_bounds__(128) stack_kernel(
    const float* __restrict__ hidden, const float* __restrict__ sp,
    const float* __restrict__ Aw, const float* __restrict__ Ab,
    const float* __restrict__ Dw, const float* __restrict__ Db,
    float* __restrict__ out)
{
    __shared__ __align__(16) float h[256];
    __shared__ __align__(16) float inp[96];
    __shared__ float ctl[3];
    const int u = blockIdx.x, tid = threadIdx.x;
    const float* hrow = hidden + (size_t)u * 256;
    h[tid] = hrow[tid]; h[tid+128] = hrow[tid+128];
    __syncthreads();
    if (tid < 96) {
        const float* w = Dw + tid * 256;
        float s = Db[tid];
        for (int k = 0; k < 256; k += 4) {
            float4 wv = *(const float4*)(w + k);
            s += wv.x*h[k] + wv.y*h[k+1] + wv.z*h[k+2] + wv.w*h[k+3];
        }
        inp[tid] = nonsat_f(s);
    } else if (tid < 99) {
        int i = tid - 96;
        const float* w = Aw + i * 256;
        float s = Ab[i];
        for (int k = 0; k < 256; k++) s += w[k]*h[k];
        ctl[i] = s;
    }
    __syncthreads();
    float mx = fmaxf(ctl[0], fmaxf(ctl[1], ctl[2]));
    float e0 = __expf(ctl[0]-mx), e1 = __expf(ctl[1]-mx), e2 = __expf(ctl[2]-mx);
    float is = __fdividef(1.f, e0+e1+e2);
    float c0 = e0*is, c1 = e1*is, c2 = e2*is;
    const float4* prev = (const float4*)(sp + (size_t)u * 4608);
    float4* dst = (float4*)(out + (size_t)u * 4608);
    const float4* inp4 = (const float4*)inp;
    for (int idx = tid; idx < 1152; idx += 128) {
        int d = idx / 24;
        float4 p = prev[idx];
        float4 up = (d == 0) ? inp4[idx] : prev[idx-24];
        float4 dn;
        if (d == 47) { dn.x=dn.y=dn.z=dn.w=0.f; } else dn = prev[idx+24];
        float4 o;
        o.x = c2*p.x + c0*up.x + c1*dn.x;
        o.y = c2*p.y + c0*up.y + c1*dn.y;
        o.z = c2*p.z + c0*up.z + c1*dn.z;
        o.w = c2*p.w + c0*up.w + c1*dn.w;
        dst[idx] = o;
    }
}

static inline void split_launch(const float* src, __nv_bfloat16* hi, __nv_bfloat16* lo, size_t n) {
    int n4 = (int)(n >> 2);
    split_kernel<<<(n4 + 255) / 256, 256>>>(src, hi, lo, n4);
}

extern "C" void kernel_launch(void* const* d_in, const int* in_sizes, int n_in,
                              void* d_out, int out_size) {
    const float* x_in = (const float*)d_in[0];
    const float* hidden_prev = (const float*)d_in[1];
    const float* stack_prev  = (const float*)d_in[2];
    const float* in_proj_w = (const float*)d_in[3];
    const float* in_proj_b = (const float*)d_in[4];
    const float* out_proj_w = (const float*)d_in[5];
    const float* out_proj_b = (const float*)d_in[6];
    const float* ln1_g = (const float*)d_in[7];
    const float* ln1_b = (const float*)d_in[8];
    const float* ln2_g = (const float*)d_in[9];
    const float* ln2_b = (const float*)d_in[10];
    const float* W_w = (const float*)d_in[11];
    const float* W_b = (const float*)d_in[12];
    const float* R_w = (const float*)d_in[13];
    const float* R_b = (const float*)d_in[14];
    const float* P_w = (const float*)d_in[15];
    const float* P_b = (const float*)d_in[16];
    const float* V_w = (const float*)d_in[17];
    const float* U_w = (const float*)d_in[18];
    const float* A_w = (const float*)d_in[19];
    const float* A_b = (const float*)d_in[20];
    const float* D_w = (const float*)d_in[21];
    const float* D_b = (const float*)d_in[22];
    const float* ffi_w = (const float*)d_in[23];
    const float* ffi_b = (const float*)d_in[24];
    const float* ffo_w = (const float*)d_in[25];
    const float* ffo_b = (const float*)d_in[26];

    static bool init_done = false;
    static float *p_proj,*p_x1,*p_lg,*p_x2,*p_ffo,*p_hb;
    static __nv_bfloat16 *pb_qkv[2],*pb_xin[2],*pb_ao[2],*pb_lg[2],*pb_x2[2],*pb_ffh[2];
    static __nv_bfloat16 *pb_hin[2],*pb_lgin[2];
    static __nv_bfloat16 *pb_w1[2],*pb_w2[2],*pb_uw[2],*pb_w3[2],*pb_w4[2],*pb_hw[2],*pb_vw[2];
    if (!init_done) {
        cudaGetSymbolAddress((void**)&p_proj, g_proj);
        cudaGetSymbolAddress((void**)&p_x1,   g_x1);
        cudaGetSymbolAddress((void**)&p_lg,   g_lg);
        cudaGetSymbolAddress((void**)&p_x2,   g_x2);
        cudaGetSymbolAddress((void**)&p_ffo,  g_ffo);
        cudaGetSymbolAddress((void**)&p_hb,   g_hb);
        __nv_bfloat16* base;
        cudaGetSymbolAddress((void**)&base, b_qkv ); pb_qkv [0]=base; pb_qkv [1]=base+(size_t)NTOK*1536;
        cudaGetSymbolAddress((void**)&base, b_xin ); pb_xin [0]=base; pb_xin [1]=base+(size_t)NTOK*512;
        cudaGetSymbolAddress((void**)&base, b_ao  ); pb_ao  [0]=base; pb_ao  [1]=base+(size_t)NTOK*512;
        cudaGetSymbolAddress((void**)&base, b_lg  ); pb_lg  [0]=base; pb_lg  [1]=base+(size_t)NTOK*128;
        cudaGetSymbolAddress((void**)&base, b_x2  ); pb_x2  [0]=base; pb_x2  [1]=base+(size_t)NTOK*512;
        cudaGetSymbolAddress((void**)&base, b_ffh ); pb_ffh [0]=base; pb_ffh [1]=base+(size_t)NTOK*2048;
        cudaGetSymbolAddress((void**)&base, b_hin ); pb_hin [0]=base; pb_hin [1]=base+(size_t)NTOK*896;
        cudaGetSymbolAddress((void**)&base, b_lgin); pb_lgin[0]=base; pb_lgin[1]=base+(size_t)NTOK*768;
        cudaGetSymbolAddress((void**)&base, b_w1  ); pb_w1  [0]=base; pb_w1  [1]=base+(size_t)1536*512;
        cudaGetSymbolAddress((void**)&base, b_w2  ); pb_w2  [0]=base; pb_w2  [1]=base+(size_t)512*512;
        cudaGetSymbolAddress((void**)&base, b_uw  ); pb_uw  [0]=base; pb_uw  [1]=base+(size_t)512*128;
        cudaGetSymbolAddress((void**)&base, b_w3  ); pb_w3  [0]=base; pb_w3  [1]=base+(size_t)2048*512;
        cudaGetSymbolAddress((void**)&base, b_w4  ); pb_w4  [0]=base; pb_w4  [1]=base+(size_t)512*2048;
        cudaGetSymbolAddress((void**)&base, b_hw  ); pb_hw  [0]=base; pb_hw  [1]=base+(size_t)256*896;
        cudaGetSymbolAddress((void**)&base, b_vw  ); pb_vw  [0]=base; pb_vw  [1]=base+(size_t)128*768;
        cudaFuncSetAttribute(tgemm<0,0>, cudaFuncAttributeMaxDynamicSharedMemorySize, T_SMEM);
        cudaFuncSetAttribute(tgemm<0,1>, cudaFuncAttributeMaxDynamicSharedMemorySize, T_SMEM);
        cudaFuncSetAttribute(tgemm<1,0>, cudaFuncAttributeMaxDynamicSharedMemorySize, T_SMEM);
        cudaFuncSetAttribute(tgemm<1,1>, cudaFuncAttributeMaxDynamicSharedMemorySize, T_SMEM);
        cudaFuncSetAttribute(tgemm<2,2>, cudaFuncAttributeMaxDynamicSharedMemorySize, T_SMEM);
        cudaFuncSetAttribute(tgemm<3,0>, cudaFuncAttributeMaxDynamicSharedMemorySize, T_SMEM);
        cudaFuncSetAttribute(attn_kernel, cudaFuncAttributeMaxDynamicSharedMemorySize, A_SMEM);
        init_done = true;
    }

    float* out_x = (float*)d_out;
    float* out_hidden = out_x + (size_t)NTOK * TE;
    float* out_stack  = out_hidden + (size_t)NTOK * TDH;

    // splits + weight packs
    split_launch(in_proj_w, pb_w1[0], pb_w1[1], (size_t)1536*512);
    split_launch(out_proj_w, pb_w2[0], pb_w2[1], (size_t)512*512);
    split_launch(U_w, pb_uw[0], pb_uw[1], (size_t)512*128);
    split_launch(ffi_w, pb_w3[0], pb_w3[1], (size_t)2048*512);
    split_launch(ffo_w, pb_w4[0], pb_w4[1], (size_t)512*2048);
    split_launch(V_w, pb_vw[0], pb_vw[1], (size_t)128*768);
    pack_hw<<<(256*448 + 255)/256, 256>>>(W_w, R_w, P_w, W_b, R_b, P_b,
                                          pb_hw[0], pb_hw[1], p_hb);
    split_launch(x_in, pb_xin[0], pb_xin[1], (size_t)NTOK*512);

    // 1) qkv (split out)
    tgemm<0,1><<<dim3(12,64),256,T_SMEM>>>(pb_xin[0], pb_xin[1], pb_w1[0], pb_w1[1],
        in_proj_b, nullptr, nullptr, pb_qkv[0], pb_qkv[1], NTOK, 1536, 512);
    // 2) flash attention
    attn_kernel<<<dim3(16,64),128,A_SMEM>>>(pb_qkv[0], pb_qkv[1], pb_ao[0], pb_ao[1]);
    // 3) out projection
    tgemm<0,0><<<dim3(4,64),256,T_SMEM>>>(pb_ao[0], pb_ao[1], pb_w2[0], pb_w2[1],
        out_proj_b, nullptr, p_proj, nullptr, nullptr, NTOK, 512, 512);
    // 4) x1 = nonsat(LN(x_in + proj))
    add_ln_kernel<true><<<NTOK,256>>>(x_in, p_proj, ln1_g, ln1_b, p_x1);
    // 5) hidden via HMMA
    pack_hidden_in<<<(NTOK*448 + 255)/256, 256>>>(p_x1, hidden_prev, stack_prev,
                                                  pb_hin[0], pb_hin[1]);
    tgemm<1,0><<<dim3(2,64),256,T_SMEM>>>(pb_hin[0], pb_hin[1], pb_hw[0], pb_hw[1],
        p_hb, nullptr, out_hidden, nullptr, nullptr, NTOK, 256, 896);
    // 6) logits via HMMA
    pack_logits_in<<<(NTOK*384 + 255)/256, 256>>>(p_x1, out_hidden, pb_lgin[0], pb_lgin[1]);
    tgemm<3,0><<<dim3(1,64),256,T_SMEM>>>(pb_lgin[0], pb_lgin[1], pb_vw[0], pb_vw[1],
        nullptr, nullptr, p_lg, nullptr, nullptr, NTOK, 128, 768);
    // 7) softmax (split out)
    softmax128_kernel<<<NTOK/8,256>>>(p_lg, pb_lg[0], pb_lg[1]);
    // 8) x2 = 0.5*(x1 + sm @ U_w.T)  (fp32 + split out)
    tgemm<2,2><<<dim3(4,64),256,T_SMEM>>>(pb_lg[0], pb_lg[1], pb_uw[0], pb_uw[1],
        nullptr, p_x1, p_x2, pb_x2[0], pb_x2[1], NTOK, 512, 128);
    // 9) stack
    stack_kernel<<<NTOK,128>>>(out_hidden, stack_prev, A_w, A_b, D_w, D_b, out_stack);
    // 10) ff hidden (split out)
    tgemm<1,1><<<dim3(16,64),256,T_SMEM>>>(pb_x2[0], pb_x2[1], pb_w3[0], pb_w3[1],
        ffi_b, nullptr, nullptr, pb_ffh[0], pb_ffh[1], NTOK, 2048, 512);
    // 11) ff out
    tgemm<0,0><<<dim3(4,64),256,T_SMEM>>>(pb_ffh[0], pb_ffh[1], pb_w4[0], pb_w4[1],
        ffo_b, nullptr, p_ffo, nullptr, nullptr, NTOK, 512, 2048);
    // 12) x_out
    add_ln_kernel<false><<<NTOK,256>>>(p_x2, p_ffo, ln2_g, ln2_b, out_x);
}